// round 4
// baseline (speedup 1.0000x reference)
#include <cuda_runtime.h>
#include <math.h>

// Problem constants
#define BB 256
#define NN 32
#define HH 256
#define FF 7
#define TT 496
#define GC 1024          // combined gemm cols: [r(256)|z(256)|i_n(256)|h_n(256)]
#define RROWS 4          // batch rows per CTA
#define NCTA (BB / RROWS)
#define EPSF 1.1920929e-07f

// -------- device scratch (no allocation allowed) --------
__device__ float g_Wc[HH * GC];     // combined node weights, k-major [k][c]
__device__ float g_Wgih[HH * GC];   // graph Wih^T padded to 1024 cols
__device__ float g_Wghh[HH * GC];   // graph Whh^T padded
__device__ float g_bvec[GC];        // combined node biases
__device__ float g_PQi[FF * 768];   // one-hot(i) column gathers of Wih_node
__device__ float g_PQj[FF * 768];   // one-hot(j) column gathers
__device__ float g_Ws1T[HH * 64];   // Ws1 transposed [k][hu]
__device__ int   g_idx[BB * NN];    // argmax of one-hot node features
__device__ int   g_rd[TT];          // adj placement rows (anti-diagonal enumeration)
__device__ int   g_cd[TT];          // adj placement cols

// -------- output layout (float32): [x 57344][adj 262144][batch 8192] --------
#define OUT_X 0
#define OUT_ADJ 57344
#define OUT_BATCH 319488

// ==================== prep kernel ====================
// Builds all derived tables + initializes output (x copy, adj zero, batch).
__global__ void prep_kernel(
    const float* __restrict__ nf,
    const float* __restrict__ Wih_n, const float* __restrict__ Whh_n,
    const float* __restrict__ bih_n, const float* __restrict__ bhh_n,
    const float* __restrict__ Wih_g, const float* __restrict__ Whh_g,
    const float* __restrict__ Ws1,
    float* __restrict__ out)
{
    long t = (long)blockIdx.x * blockDim.x + threadIdx.x;

    if (t < 262144) {  // g_Wc
        int k = (int)(t >> 10), c = (int)(t & 1023);
        float v;
        if (c < 512)       v = Wih_n[c * 270 + 14 + k] + Whh_n[c * 256 + k]; // r,z combined
        else if (c < 768)  v = Wih_n[c * 270 + 14 + k];                      // i_n
        else               v = Whh_n[(c - 256) * 256 + k];                   // h_n
        g_Wc[t] = v; return;
    }
    t -= 262144;
    if (t < 262144) {  // g_Wgih (transposed, padded)
        int k = (int)(t >> 10), c = (int)(t & 1023);
        g_Wgih[t] = (c < 768) ? Wih_g[c * 256 + k] : 0.f; return;
    }
    t -= 262144;
    if (t < 262144) {  // g_Wghh
        int k = (int)(t >> 10), c = (int)(t & 1023);
        g_Wghh[t] = (c < 768) ? Whh_g[c * 256 + k] : 0.f; return;
    }
    t -= 262144;
    if (t < 1024) {    // g_bvec
        int c = (int)t; float v;
        if (c < 512)      v = bih_n[c] + bhh_n[c];
        else if (c < 768) v = bih_n[c];
        else              v = bhh_n[c - 256];
        g_bvec[c] = v; return;
    }
    t -= 1024;
    if (t < FF * 768) { int f = (int)(t / 768), c = (int)(t % 768);
        g_PQi[t] = Wih_n[c * 270 + f]; return; }
    t -= FF * 768;
    if (t < FF * 768) { int f = (int)(t / 768), c = (int)(t % 768);
        g_PQj[t] = Wih_n[c * 270 + 7 + f]; return; }
    t -= FF * 768;
    if (t < 16384) {   // Ws1T[k][hu]
        int k = (int)(t >> 6), hu = (int)(t & 63);
        g_Ws1T[t] = Ws1[hu * 256 + k]; return;
    }
    t -= 16384;
    if (t < BB * NN) { // argmax one-hot
        const float* p = nf + t * FF;
        int best = 0;
        #pragma unroll
        for (int f = 0; f < FF; f++) if (p[f] > 0.5f) best = f;
        g_idx[t] = best; return;
    }
    t -= BB * NN;
    if (t < TT) {      // anti-diagonal placement tables
        int m = (int)t;
        int d = (int)((1.0 + sqrt(1.0 + 8.0 * (double)m)) * 0.5);
        while (d * (d - 1) / 2 > m) d--;
        while ((d + 1) * d / 2 <= m) d++;
        int rr = m - d * (d - 1) / 2;
        g_rd[m] = rr; g_cd[m] = rr + NN - d; return;
    }
    t -= TT;
    if (t < BB * NN * FF) { out[OUT_X + t] = nf[t]; return; }   // x
    t -= BB * NN * FF;
    if (t < BB * NN * NN) { out[OUT_ADJ + t] = 0.f; return; }   // adj zero
    t -= BB * NN * NN;
    if (t < BB * NN) { out[OUT_BATCH + t] = (float)(t >> 5); return; } // batch
}

// ==================== main persistent chain kernel ====================
__device__ __forceinline__ float sigm(float x) { return 1.f / (1.f + expf(-x)); }

// [RROWS rows] x [4 cols per thread] x K=256 GEMM; h staged transposed in smem
__device__ __forceinline__ void gemm4(const float* __restrict__ Wbase,
                                      const float* __restrict__ shT,
                                      float acc[RROWS][4])
{
    #pragma unroll
    for (int r = 0; r < RROWS; r++)
        #pragma unroll
        for (int q = 0; q < 4; q++) acc[r][q] = 0.f;
    #pragma unroll 8
    for (int k = 0; k < HH; k++) {
        float4 w = *reinterpret_cast<const float4*>(Wbase + (long)k * GC);
        float4 h = *reinterpret_cast<const float4*>(shT + k * 4);
        float hv[4] = {h.x, h.y, h.z, h.w};
        #pragma unroll
        for (int r = 0; r < RROWS; r++) {
            acc[r][0] = fmaf(hv[r], w.x, acc[r][0]);
            acc[r][1] = fmaf(hv[r], w.y, acc[r][1]);
            acc[r][2] = fmaf(hv[r], w.z, acc[r][2]);
            acc[r][3] = fmaf(hv[r], w.w, acc[r][3]);
        }
    }
}

// smem float offsets
#define SO_PQI 0
#define SO_PQJ (SO_PQI + FF*768)          // 5376
#define SO_BV  (SO_PQJ + FF*768)          // 10752
#define SO_W1T (SO_BV + GC)               // 11776
#define SO_HT  (SO_W1T + 16384)           // 28160
#define SO_GHT (SO_HT + HH*RROWS)         // 29184
#define SO_G   (SO_GHT + HH*RROWS)        // 30208 (gates: RROWS * 2048)
#define SO_BGI (SO_G + RROWS*2048)        // 38400
#define SO_BGH (SO_BGI + 768)             // 39168
#define SO_HID (SO_BGH + 768)             // 39936
#define SO_W2  (SO_HID + RROWS*64)        // 40192
#define SO_B1  (SO_W2 + 64)               // 40256
#define SO_IDX (SO_B1 + 64)               // 40320 (128 ints)
#define SMEM_FLOATS (SO_IDX + 128)        // 40448
#define SMEM_BYTES (SMEM_FLOATS * 4)      // 161792

__global__ void __launch_bounds__(256, 1) chain_kernel(
    const float* __restrict__ z, const float* __restrict__ u,
    const float* __restrict__ bih_g, const float* __restrict__ bhh_g,
    const float* __restrict__ bs1, const float* __restrict__ Ws2,
    const float* __restrict__ bs2, float* __restrict__ out)
{
    extern __shared__ float sm[];
    float* sPQi = sm + SO_PQI;
    float* sPQj = sm + SO_PQJ;
    float* sbv  = sm + SO_BV;
    float* sW1T = sm + SO_W1T;
    float* shT  = sm + SO_HT;    // node_h transposed [k][row]
    float* sghT = sm + SO_GHT;   // graph_h transposed
    float* sg   = sm + SO_G;     // gate staging [row][2048]
    float* sbgi = sm + SO_BGI;
    float* sbgh = sm + SO_BGH;
    float* shid = sm + SO_HID;
    float* sw2  = sm + SO_W2;
    float* sb1  = sm + SO_B1;
    int*   sidx = (int*)(sm + SO_IDX);

    const int t = threadIdx.x;
    const int b0 = blockIdx.x * RROWS;

    for (int x = t; x < FF*768; x += 256) { sPQi[x] = g_PQi[x]; sPQj[x] = g_PQj[x]; }
    for (int x = t; x < GC; x += 256) sbv[x] = g_bvec[x];
    for (int x = t; x < 16384; x += 256) sW1T[x] = g_Ws1T[x];
    for (int x = t; x < HH*RROWS; x += 256) {
        int k = x >> 2, r = x & 3;
        sghT[x] = z[(b0 + r) * HH + k];
    }
    for (int x = t; x < 768; x += 256) { sbgi[x] = bih_g[x]; sbgh[x] = bhh_g[x]; }
    if (t < 64) { sw2[t] = Ws2[t]; sb1[t] = bs1[t]; }
    for (int x = t; x < RROWS*NN; x += 256) sidx[x] = g_idx[b0 * NN + x];
    const float bs2v = *bs2;
    __syncthreads();

    const int c0 = t * 4;                 // this thread's 4 gemm columns
    const int arow = t >> 6;              // activation: row
    const int hc0 = (t & 63) * 4;         // activation: 4 h-columns

    for (int i = 0; i < NN - 1; i++) {
        // node_h := graph_h
        for (int x = t; x < HH*RROWS; x += 256) shT[x] = sghT[x];
        __syncthreads();

        int fi[RROWS];
        #pragma unroll
        for (int r = 0; r < RROWS; r++) fi[r] = sidx[r * NN + i];

        for (int j = i + 1; j < NN; j++) {
            float acc[RROWS][4];
            gemm4(g_Wc + c0, shT, acc);

            int fj[RROWS];
            #pragma unroll
            for (int r = 0; r < RROWS; r++) fj[r] = sidx[r * NN + j];

            // stage gates (+ one-hot gathers + biases)
            #pragma unroll
            for (int q = 0; q < 4; q++) {
                int c = c0 + q;
                float base = sbv[c];
                #pragma unroll
                for (int r = 0; r < RROWS; r++) {
                    float v = acc[r][q] + base;
                    if (c < 768)
                        v += sPQi[fi[r] * 768 + c] + sPQj[fj[r] * 768 + c];
                    sg[r * 2048 + c] = v;
                }
            }
            __syncthreads();

            // GRU activation: update node_h
            #pragma unroll
            for (int q = 0; q < 4; q++) {
                int hc = hc0 + q;
                const float* gr_ = sg + arow * 2048;
                float gr = sigm(gr_[hc]);
                float gz = sigm(gr_[256 + hc]);
                float gn = tanhf(gr_[512 + hc] + gr * gr_[768 + hc]);
                float ho = shT[hc * 4 + arow];
                shT[hc * 4 + arow] = (1.f - gz) * gn + gz * ho;
            }
            __syncthreads();

            // score head: hid = relu(h @ Ws1^T + bs1)
            {
                int hu = t & 63, row = t >> 6;
                float a = 0.f;
                #pragma unroll 4
                for (int k = 0; k < HH; k++)
                    a = fmaf(sW1T[k * 64 + hu], shT[k * 4 + row], a);
                shid[row * 64 + hu] = fmaxf(a + sb1[hu], 0.f);
            }
            __syncthreads();

            if (t < 128) {
                int row = t >> 5, l = t & 31;
                float s = shid[row * 64 + l] * sw2[l]
                        + shid[row * 64 + 32 + l] * sw2[32 + l];
                #pragma unroll
                for (int o = 16; o; o >>= 1) s += __shfl_down_sync(0xffffffffu, s, o);
                if (l == 0) {
                    float prob = sigm(s + bs2v);
                    int m = i * (NN - 1) - (i * (i - 1)) / 2 + (j - i - 1);
                    int b = b0 + row;
                    float uu = u[b * TT + m];
                    float p = fminf(fmaxf(prob, EPSF), 1.f - EPSF);
                    float e;
                    if (p < 0.499f || p > 0.501f) {
                        e = (log1pf(-p + uu * (2.f * p - 1.f)) - log1pf(-p))
                          / (logf(p) - log1pf(-p));
                    } else {
                        e = uu;
                    }
                    int rr = g_rd[m], cc = g_cd[m];
                    float* adj = out + OUT_ADJ + b * (NN * NN);
                    adj[rr * NN + cc] = e;
                    adj[cc * NN + rr] = e;
                }
            }
            __syncthreads();
        }

        // graph GRU: graph_h = GRU_g(x=node_h, h=graph_h)   (skip unused last)
        if (i < NN - 2) {
            float acc[RROWS][4];
            gemm4(g_Wgih + c0, shT, acc);
            #pragma unroll
            for (int q = 0; q < 4; q++)
                #pragma unroll
                for (int r = 0; r < RROWS; r++)
                    sg[r * 2048 + c0 + q] = acc[r][q];
            gemm4(g_Wghh + c0, sghT, acc);
            #pragma unroll
            for (int q = 0; q < 4; q++)
                #pragma unroll
                for (int r = 0; r < RROWS; r++)
                    sg[r * 2048 + 1024 + c0 + q] = acc[r][q];
            __syncthreads();

            #pragma unroll
            for (int q = 0; q < 4; q++) {
                int hc = hc0 + q;
                const float* gi_ = sg + arow * 2048;
                const float* gh_ = gi_ + 1024;
                float rr = sigm(gi_[hc] + sbgi[hc] + gh_[hc] + sbgh[hc]);
                float zz = sigm(gi_[256 + hc] + sbgi[256 + hc]
                              + gh_[256 + hc] + sbgh[256 + hc]);
                float nn = tanhf(gi_[512 + hc] + sbgi[512 + hc]
                               + rr * (gh_[512 + hc] + sbgh[512 + hc]));
                float ho = sghT[hc * 4 + arow];
                sghT[hc * 4 + arow] = (1.f - zz) * nn + zz * ho;
            }
            __syncthreads();
        }
    }
}

// ==================== launch ====================
extern "C" void kernel_launch(void* const* d_in, const int* in_sizes, int n_in,
                              void* d_out, int out_size)
{
    const float* z     = (const float*)d_in[0];
    const float* nf    = (const float*)d_in[1];
    const float* u     = (const float*)d_in[2];
    const float* Wih_n = (const float*)d_in[3];
    const float* Whh_n = (const float*)d_in[4];
    const float* bih_n = (const float*)d_in[5];
    const float* bhh_n = (const float*)d_in[6];
    const float* Wih_g = (const float*)d_in[7];
    const float* Whh_g = (const float*)d_in[8];
    const float* bih_g = (const float*)d_in[9];
    const float* bhh_g = (const float*)d_in[10];
    const float* Ws1   = (const float*)d_in[11];
    const float* bs1   = (const float*)d_in[12];
    const float* Ws2   = (const float*)d_in[13];
    const float* bs2   = (const float*)d_in[14];
    float* out = (float*)d_out;

    // total prep work items
    const long total = 262144L*3 + 1024 + FF*768*2 + 16384 + BB*NN + TT
                     + BB*NN*FF + BB*NN*NN + BB*NN;
    int blocks = (int)((total + 255) / 256);
    prep_kernel<<<blocks, 256>>>(nf, Wih_n, Whh_n, bih_n, bhh_n,
                                 Wih_g, Whh_g, Ws1, out);

    cudaFuncSetAttribute(chain_kernel,
                         cudaFuncAttributeMaxDynamicSharedMemorySize, SMEM_BYTES);
    chain_kernel<<<NCTA, 256, SMEM_BYTES>>>(z, u, bih_g, bhh_g, bs1, Ws2, bs2, out);
}

// round 5
// speedup vs baseline: 1.0748x; 1.0748x over previous
#include <cuda_runtime.h>
#include <math.h>

// ---------------- problem constants ----------------
#define BB 256
#define NN 32
#define HH 256
#define FF 7
#define TT 496
#define RROWS 4            // batch rows per cluster
#define NCLUST (BB / RROWS)    // 64 clusters
#define NCTA (NCLUST * 2)      // 128 CTAs
#define LC 512                 // local gemm columns per CTA (half of 1024)
#define WC_K 32                // k-rows of node weights cached in smem
#define EPSF 1.1920929e-07f

// ---------------- device scratch ----------------
__device__ float g_Wc2[2 * HH * LC];    // node combined weights, [half][k][lc]
__device__ float g_Wgih2[2 * HH * LC];  // graph Wih, [half][k][lc], gate3 = 0
__device__ float g_Wghh2[2 * HH * LC];  // graph Whh
__device__ float g_bv2[2 * LC];         // node combined biases per half
__device__ float g_bgi2[2 * LC];        // graph ih biases per half (gate3=0)
__device__ float g_bgh2[2 * LC];        // graph hh biases per half
__device__ float g_PQi2[2 * FF * LC];   // one-hot(i) gathers per half (gate3=0)
__device__ float g_PQj2[2 * FF * LC];
__device__ float g_Ws1T[HH * 64];       // Ws1 transposed [k][hu]
__device__ int   g_idx[BB * NN];
__device__ int   g_rd[TT];
__device__ int   g_cd[TT];

// output layout (float32): [x 57344][adj 262144][batch 8192]
#define OUT_X 0
#define OUT_ADJ 57344
#define OUT_BATCH 319488

// ==================== prep kernel ====================
__global__ void prep_kernel(
    const float* __restrict__ nf,
    const float* __restrict__ Wih_n, const float* __restrict__ Whh_n,
    const float* __restrict__ bih_n, const float* __restrict__ bhh_n,
    const float* __restrict__ Wih_g, const float* __restrict__ Whh_g,
    const float* __restrict__ bih_g, const float* __restrict__ bhh_g,
    const float* __restrict__ Ws1,
    float* __restrict__ out)
{
    long t = (long)blockIdx.x * blockDim.x + threadIdx.x;

    if (t < 262144) {   // g_Wc2
        int half = (int)(t >> 17), rem = (int)(t & 131071);
        int k = rem >> 9, lc = rem & 511;
        int g = lc >> 7, hc = half * 128 + (lc & 127);
        float v;
        if (g < 2)       v = Wih_n[(g*256 + hc) * 270 + 14 + k] + Whh_n[(g*256 + hc) * 256 + k];
        else if (g == 2) v = Wih_n[(512 + hc) * 270 + 14 + k];
        else             v = Whh_n[(512 + hc) * 256 + k];
        g_Wc2[t] = v; return;
    }
    t -= 262144;
    if (t < 262144) {   // g_Wgih2
        int half = (int)(t >> 17), rem = (int)(t & 131071);
        int k = rem >> 9, lc = rem & 511;
        int g = lc >> 7, hc = half * 128 + (lc & 127);
        g_Wgih2[t] = (g < 3) ? Wih_g[(g*256 + hc) * 256 + k] : 0.f; return;
    }
    t -= 262144;
    if (t < 262144) {   // g_Wghh2
        int half = (int)(t >> 17), rem = (int)(t & 131071);
        int k = rem >> 9, lc = rem & 511;
        int g = lc >> 7, hc = half * 128 + (lc & 127);
        g_Wghh2[t] = (g < 3) ? Whh_g[(g*256 + hc) * 256 + k] : 0.f; return;
    }
    t -= 262144;
    if (t < 1024) {     // g_bv2
        int half = (int)(t >> 9), lc = (int)(t & 511);
        int g = lc >> 7, hc = half * 128 + (lc & 127);
        float v;
        if (g < 2)       v = bih_n[g*256 + hc] + bhh_n[g*256 + hc];
        else if (g == 2) v = bih_n[512 + hc];
        else             v = bhh_n[512 + hc];
        g_bv2[t] = v; return;
    }
    t -= 1024;
    if (t < 1024) {     // g_bgi2
        int half = (int)(t >> 9), lc = (int)(t & 511);
        int g = lc >> 7, hc = half * 128 + (lc & 127);
        g_bgi2[t] = (g < 3) ? bih_g[g*256 + hc] : 0.f; return;
    }
    t -= 1024;
    if (t < 1024) {     // g_bgh2
        int half = (int)(t >> 9), lc = (int)(t & 511);
        int g = lc >> 7, hc = half * 128 + (lc & 127);
        g_bgh2[t] = (g < 3) ? bhh_g[g*256 + hc] : 0.f; return;
    }
    t -= 1024;
    if (t < 7168) {     // g_PQi2
        int half = (int)(t / 3584), rem = (int)(t % 3584);
        int f = rem / 512, lc = rem % 512;
        int g = lc >> 7, hc = half * 128 + (lc & 127);
        g_PQi2[t] = (g < 3) ? Wih_n[(g*256 + hc) * 270 + f] : 0.f; return;
    }
    t -= 7168;
    if (t < 7168) {     // g_PQj2
        int half = (int)(t / 3584), rem = (int)(t % 3584);
        int f = rem / 512, lc = rem % 512;
        int g = lc >> 7, hc = half * 128 + (lc & 127);
        g_PQj2[t] = (g < 3) ? Wih_n[(g*256 + hc) * 270 + 7 + f] : 0.f; return;
    }
    t -= 7168;
    if (t < 16384) {    // Ws1T
        int k = (int)(t >> 6), hu = (int)(t & 63);
        g_Ws1T[t] = Ws1[hu * 256 + k]; return;
    }
    t -= 16384;
    if (t < BB * NN) {  // argmax one-hot
        const float* p = nf + t * FF;
        int best = 0;
        #pragma unroll
        for (int f = 0; f < FF; f++) if (p[f] > 0.5f) best = f;
        g_idx[t] = best; return;
    }
    t -= BB * NN;
    if (t < TT) {       // anti-diagonal placement
        int m = (int)t;
        int d = (int)((1.0 + sqrt(1.0 + 8.0 * (double)m)) * 0.5);
        while (d * (d - 1) / 2 > m) d--;
        while ((d + 1) * d / 2 <= m) d++;
        int rr = m - d * (d - 1) / 2;
        g_rd[m] = rr; g_cd[m] = rr + NN - d; return;
    }
    t -= TT;
    if (t < BB * NN * FF) { out[OUT_X + t] = nf[t]; return; }
    t -= BB * NN * FF;
    if (t < BB * NN * NN) { out[OUT_ADJ + t] = 0.f; return; }
    t -= BB * NN * NN;
    if (t < BB * NN) { out[OUT_BATCH + t] = (float)(t >> 5); return; }
}

// ==================== helpers ====================
__device__ __forceinline__ float sigm(float x) { return 1.f / (1.f + expf(-x)); }

__device__ __forceinline__ void ffma2(unsigned long long& d,
                                      unsigned long long a, unsigned long long b) {
    asm("fma.rn.f32x2 %0, %1, %2, %0;" : "+l"(d) : "l"(a), "l"(b));
}

__device__ __forceinline__ float2 unpk(unsigned long long v) {
    float2 r;
    r.x = __uint_as_float((unsigned)(v & 0xffffffffu));
    r.y = __uint_as_float((unsigned)(v >> 32));
    return r;
}

__device__ __forceinline__ void st_peer64(float* p, unsigned peer, float lo, float hi) {
    unsigned la = (unsigned)__cvta_generic_to_shared(p);
    unsigned ra;
    asm volatile("mapa.shared::cluster.u32 %0, %1, %2;" : "=r"(ra) : "r"(la), "r"(peer));
    unsigned long long bits = ((unsigned long long)__float_as_uint(hi) << 32)
                            | (unsigned long long)__float_as_uint(lo);
    asm volatile("st.shared::cluster.b64 [%0], %1;" :: "r"(ra), "l"(bits) : "memory");
}

#define CLUSTER_SYNC() do { \
    asm volatile("barrier.cluster.arrive.aligned;" ::: "memory"); \
    asm volatile("barrier.cluster.wait.aligned;" ::: "memory"); } while (0)

// GEMM: acc[4 rows] of 2 packed cols per thread, K=256, h in dup-pair layout [k][8]
template <int KSM>
__device__ __forceinline__ void gemm512(const float* __restrict__ Wglob,
                                        const float* __restrict__ Wsm,
                                        const float* __restrict__ hb,
                                        int t,
                                        unsigned long long& a0, unsigned long long& a1,
                                        unsigned long long& a2, unsigned long long& a3)
{
    a0 = a1 = a2 = a3 = 0ull;
    if (KSM > 0) {
        const float* ws = Wsm + 2 * t;
        #pragma unroll 8
        for (int k = 0; k < KSM; k++) {
            unsigned long long w = *(const unsigned long long*)(ws + k * LC);
            ulonglong2 h01 = *(const ulonglong2*)(hb + k * 8);
            ulonglong2 h23 = *(const ulonglong2*)(hb + k * 8 + 4);
            ffma2(a0, w, h01.x); ffma2(a1, w, h01.y);
            ffma2(a2, w, h23.x); ffma2(a3, w, h23.y);
        }
    }
    const unsigned long long* wg = (const unsigned long long*)Wglob + t;
    #pragma unroll 8
    for (int k = KSM; k < HH; k++) {
        unsigned long long w = wg[k * (LC / 2)];
        ulonglong2 h01 = *(const ulonglong2*)(hb + k * 8);
        ulonglong2 h23 = *(const ulonglong2*)(hb + k * 8 + 4);
        ffma2(a0, w, h01.x); ffma2(a1, w, h01.y);
        ffma2(a2, w, h23.x); ffma2(a3, w, h23.y);
    }
}

// ---------------- smem layout (float offsets) ----------------
#define SO_WC   0
#define SO_W1T  (SO_WC  + WC_K * LC)     // 16384
#define SO_PQI  (SO_W1T + 16384)         // 32768
#define SO_PQJ  (SO_PQI + FF * LC)       // 36352
#define SO_H0   (SO_PQJ + FF * LC)       // 39936
#define SO_H1   (SO_H0 + 2048)           // 41984
#define SO_GH0  (SO_H1 + 2048)           // 44032
#define SO_GH1  (SO_GH0 + 2048)          // 46080
#define SO_SG   (SO_GH1 + 2048)          // 48128
#define SO_SG2  (SO_SG + RROWS * LC)     // 50176
#define SO_BV   (SO_SG2 + RROWS * LC)    // 52224
#define SO_BGI  (SO_BV + LC)             // 52736
#define SO_BGH  (SO_BGI + LC)            // 53248
#define SO_HID  (SO_BGH + LC)            // 53760
#define SO_W2   (SO_HID + RROWS * 64)    // 54016
#define SO_B1   (SO_W2 + 64)             // 54080
#define SO_IDX  (SO_B1 + 64)             // 54144 (128 ints)
#define SMEM_FLOATS (SO_IDX + 128)       // 54272
#define SMEM_BYTES (SMEM_FLOATS * 4)     // 217088

// ==================== main chain kernel ====================
__global__ void __launch_bounds__(256, 1) __cluster_dims__(2, 1, 1)
chain_kernel(const float* __restrict__ z, const float* __restrict__ u,
             const float* __restrict__ Ws2, const float* __restrict__ bs1,
             const float* __restrict__ bs2, float* __restrict__ out)
{
    extern __shared__ float sm[];
    float* sWc  = sm + SO_WC;
    float* sW1T = sm + SO_W1T;
    float* sPQi = sm + SO_PQI;
    float* sPQj = sm + SO_PQJ;
    float* shB[2] = { sm + SO_H0, sm + SO_H1 };
    float* sghB[2] = { sm + SO_GH0, sm + SO_GH1 };
    float* sg   = sm + SO_SG;
    float* sg2  = sm + SO_SG2;
    float* sbv  = sm + SO_BV;
    float* sbgi = sm + SO_BGI;
    float* sbgh = sm + SO_BGH;
    float* shid = sm + SO_HID;
    float* sw2  = sm + SO_W2;
    float* sb1  = sm + SO_B1;
    int*   sidx = (int*)(sm + SO_IDX);

    const int t = threadIdx.x;
    const int half = blockIdx.x & 1;      // cluster cta rank
    const unsigned peer = half ^ 1;
    const int cid = blockIdx.x >> 1;
    const int b0 = cid * RROWS;

    const float* WcG  = g_Wc2 + half * (HH * LC);
    const float* WgiG = g_Wgih2 + half * (HH * LC);
    const float* WghG = g_Wghh2 + half * (HH * LC);

    for (int x = t; x < WC_K * LC; x += 256) sWc[x] = WcG[x];
    for (int x = t; x < 16384; x += 256) sW1T[x] = g_Ws1T[x];
    for (int x = t; x < FF * LC; x += 256) {
        sPQi[x] = g_PQi2[half * FF * LC + x];
        sPQj[x] = g_PQj2[half * FF * LC + x];
    }
    for (int x = t; x < 2048; x += 256) {     // graph h init (dup-pair layout)
        int k = x >> 3, r = (x & 7) >> 1;
        sghB[0][x] = z[(b0 + r) * HH + k];
    }
    for (int x = t; x < LC; x += 256) {
        sbv[x]  = g_bv2[half * LC + x];
        sbgi[x] = g_bgi2[half * LC + x];
        sbgh[x] = g_bgh2[half * LC + x];
    }
    if (t < 64) { sw2[t] = Ws2[t]; sb1[t] = bs1[t]; }
    if (t < RROWS * NN) sidx[t] = g_idx[b0 * NN + t];
    const float bs2v = *bs2;
    __syncthreads();
    CLUSTER_SYNC();

    int pb = 0, gpb = 0;
    const int lc0 = t * 2;
    const int hcl = t & 127;
    const int hc = half * 128 + hcl;
    const int rbase = (t >> 7) * 2;

    for (int i = 0; i < NN - 1; i++) {
        // node_h := graph_h
        {
            const float* gsrc = sghB[gpb];
            float* dst = shB[pb];
            for (int x = t; x < 2048; x += 256) dst[x] = gsrc[x];
        }
        __syncthreads();

        const int fi0 = sidx[i], fi1 = sidx[NN + i], fi2 = sidx[2*NN + i], fi3 = sidx[3*NN + i];

        for (int j = i + 1; j < NN; j++) {
            float* hr = shB[pb];
            float* hw = shB[pb ^ 1];

            unsigned long long a0, a1, a2, a3;
            gemm512<WC_K>(WcG, sWc, hr, t, a0, a1, a2, a3);

            // stage gates (+ biases + one-hot gathers)
            {
                const int fj0 = sidx[j], fj1 = sidx[NN + j], fj2 = sidx[2*NN + j], fj3 = sidx[3*NN + j];
                float2 v0 = unpk(a0), v1 = unpk(a1), v2 = unpk(a2), v3 = unpk(a3);
                float bvx = sbv[lc0], bvy = sbv[lc0 + 1];
                sg[lc0]           = v0.x + bvx + sPQi[fi0*LC + lc0]   + sPQj[fj0*LC + lc0];
                sg[lc0 + 1]       = v0.y + bvy + sPQi[fi0*LC + lc0+1] + sPQj[fj0*LC + lc0+1];
                sg[LC + lc0]      = v1.x + bvx + sPQi[fi1*LC + lc0]   + sPQj[fj1*LC + lc0];
                sg[LC + lc0 + 1]  = v1.y + bvy + sPQi[fi1*LC + lc0+1] + sPQj[fj1*LC + lc0+1];
                sg[2*LC + lc0]    = v2.x + bvx + sPQi[fi2*LC + lc0]   + sPQj[fj2*LC + lc0];
                sg[2*LC + lc0 +1] = v2.y + bvy + sPQi[fi2*LC + lc0+1] + sPQj[fj2*LC + lc0+1];
                sg[3*LC + lc0]    = v3.x + bvx + sPQi[fi3*LC + lc0]   + sPQj[fj3*LC + lc0];
                sg[3*LC + lc0 +1] = v3.y + bvy + sPQi[fi3*LC + lc0+1] + sPQj[fj3*LC + lc0+1];
            }
            __syncthreads();

            // GRU activation on local 128 h-columns, 2 rows per thread
            #pragma unroll
            for (int r = rbase; r < rbase + 2; r++) {
                float gr = sigm(sg[r*LC + hcl]);
                float gz = sigm(sg[r*LC + 128 + hcl]);
                float gn = tanhf(sg[r*LC + 256 + hcl] + gr * sg[r*LC + 384 + hcl]);
                float ho = hr[hc * 8 + 2 * r];
                float hn = (1.f - gz) * gn + gz * ho;
                float* dp = hw + hc * 8 + 2 * r;
                dp[0] = hn; dp[1] = hn;
                st_peer64(dp, peer, hn, hn);
            }
            CLUSTER_SYNC();

            // score head + edge sample (rank 0 only)
            if (half == 0) {
                const int hu = t & 63, row = t >> 6;
                float a = 0.f;
                #pragma unroll 8
                for (int k = 0; k < HH; k++)
                    a = fmaf(sW1T[k * 64 + hu], hw[k * 8 + 2 * row], a);
                shid[row * 64 + hu] = fmaxf(a + sb1[hu], 0.f);
                __syncthreads();

                if (t < 128) {
                    const int row2 = t >> 5, l = t & 31;
                    float s = shid[row2 * 64 + l] * sw2[l]
                            + shid[row2 * 64 + 32 + l] * sw2[32 + l];
                    #pragma unroll
                    for (int o = 16; o; o >>= 1) s += __shfl_down_sync(0xffffffffu, s, o);
                    if (l == 0) {
                        float prob = sigm(s + bs2v);
                        int m = i * (NN - 1) - (i * (i - 1)) / 2 + (j - i - 1);
                        int b = b0 + row2;
                        float uu = u[b * TT + m];
                        float p = fminf(fmaxf(prob, EPSF), 1.f - EPSF);
                        float e;
                        if (p < 0.499f || p > 0.501f) {
                            e = (log1pf(-p + uu * (2.f * p - 1.f)) - log1pf(-p))
                              / (logf(p) - log1pf(-p));
                        } else {
                            e = uu;
                        }
                        int rr = g_rd[m], cc = g_cd[m];
                        float* adj = out + OUT_ADJ + b * (NN * NN);
                        adj[rr * NN + cc] = e;
                        adj[cc * NN + rr] = e;
                    }
                }
            }
            pb ^= 1;
        }

        // graph GRU (skip last unused update)
        if (i < NN - 2) {
            float* hfin = shB[pb];
            const float* ghr = sghB[gpb];
            float* ghw = sghB[gpb ^ 1];

            unsigned long long a0, a1, a2, a3;
            gemm512<0>(WgiG, nullptr, hfin, t, a0, a1, a2, a3);
            {
                float2 v0 = unpk(a0), v1 = unpk(a1), v2 = unpk(a2), v3 = unpk(a3);
                sg[lc0] = v0.x;        sg[lc0+1] = v0.y;
                sg[LC+lc0] = v1.x;     sg[LC+lc0+1] = v1.y;
                sg[2*LC+lc0] = v2.x;   sg[2*LC+lc0+1] = v2.y;
                sg[3*LC+lc0] = v3.x;   sg[3*LC+lc0+1] = v3.y;
            }
            gemm512<0>(WghG, nullptr, ghr, t, a0, a1, a2, a3);
            {
                float2 v0 = unpk(a0), v1 = unpk(a1), v2 = unpk(a2), v3 = unpk(a3);
                sg2[lc0] = v0.x;        sg2[lc0+1] = v0.y;
                sg2[LC+lc0] = v1.x;     sg2[LC+lc0+1] = v1.y;
                sg2[2*LC+lc0] = v2.x;   sg2[2*LC+lc0+1] = v2.y;
                sg2[3*LC+lc0] = v3.x;   sg2[3*LC+lc0+1] = v3.y;
            }
            __syncthreads();

            #pragma unroll
            for (int r = rbase; r < rbase + 2; r++) {
                float rr = sigm(sg[r*LC + hcl] + sbgi[hcl]
                              + sg2[r*LC + hcl] + sbgh[hcl]);
                float zz = sigm(sg[r*LC + 128 + hcl] + sbgi[128 + hcl]
                              + sg2[r*LC + 128 + hcl] + sbgh[128 + hcl]);
                float nn = tanhf(sg[r*LC + 256 + hcl] + sbgi[256 + hcl]
                               + rr * (sg2[r*LC + 256 + hcl] + sbgh[256 + hcl]));
                float go = ghr[hc * 8 + 2 * r];
                float gh = (1.f - zz) * nn + zz * go;
                float* dp = ghw + hc * 8 + 2 * r;
                dp[0] = gh; dp[1] = gh;
                st_peer64(dp, peer, gh, gh);
            }
            CLUSTER_SYNC();
            gpb ^= 1;
        }
    }
}

// ==================== launch ====================
extern "C" void kernel_launch(void* const* d_in, const int* in_sizes, int n_in,
                              void* d_out, int out_size)
{
    const float* z     = (const float*)d_in[0];
    const float* nf    = (const float*)d_in[1];
    const float* u     = (const float*)d_in[2];
    const float* Wih_n = (const float*)d_in[3];
    const float* Whh_n = (const float*)d_in[4];
    const float* bih_n = (const float*)d_in[5];
    const float* bhh_n = (const float*)d_in[6];
    const float* Wih_g = (const float*)d_in[7];
    const float* Whh_g = (const float*)d_in[8];
    const float* bih_g = (const float*)d_in[9];
    const float* bhh_g = (const float*)d_in[10];
    const float* Ws1   = (const float*)d_in[11];
    const float* bs1   = (const float*)d_in[12];
    const float* Ws2   = (const float*)d_in[13];
    const float* bs2   = (const float*)d_in[14];
    float* out = (float*)d_out;

    const long total = 262144L * 3 + 1024 * 3 + 7168 * 2 + 16384
                     + BB * NN + TT + BB * NN * FF + BB * NN * NN + BB * NN;
    int blocks = (int)((total + 255) / 256);
    prep_kernel<<<blocks, 256>>>(nf, Wih_n, Whh_n, bih_n, bhh_n,
                                 Wih_g, Whh_g, bih_g, bhh_g, Ws1, out);

    cudaFuncSetAttribute(chain_kernel,
                         cudaFuncAttributeMaxDynamicSharedMemorySize, SMEM_BYTES);
    chain_kernel<<<NCTA, 256, SMEM_BYTES>>>(z, u, Ws2, bs1, bs2, out);
}

// round 6
// speedup vs baseline: 1.1492x; 1.0692x over previous
#include <cuda_runtime.h>
#include <math.h>

// ---------------- problem constants ----------------
#define BB 256
#define NN 32
#define HH 256
#define FF 7
#define TT 496
#define RR 8                 // batch rows per 4-CTA cluster
#define NCLUST (BB / RR)     // 32 clusters
#define NCTA (NCLUST * 4)    // 128 CTAs
#define LCN 256              // node gemm local cols per CTA (4 gate-groups x 64)
#define LCG 192              // graph gemm local cols per matrix (3 groups x 64)
#define KRES 96              // k-rows of node weights resident in smem
#define TAILB ((HH - KRES) / 16)   // 10 tail blocks of 16
#define EPSF 1.1920929e-07f

// ---------------- device scratch ----------------
__device__ float g_Wc4[4 * HH * LCN];    // node combined weights [q][k][lc]
__device__ float g_Wgi4[4 * HH * LCG];   // graph Wih slice [q][k][lc]
__device__ float g_Wgh4[4 * HH * LCG];   // graph Whh slice
__device__ float g_bv4[4 * LCN];         // node combined bias [q][lc]
__device__ float g_bgi4[4 * LCG];        // graph ih bias
__device__ float g_bgh4[4 * LCG];        // graph hh bias
__device__ float g_PQi4[4 * FF * LCN];   // one-hot(i) gathers [q][f][lc] (g3=0)
__device__ float g_PQj4[4 * FF * LCN];
__device__ float g_Ws1T[HH * 64];        // Ws1 transposed [k][u]
__device__ int   g_idx[BB * NN];
__device__ int   g_rd[TT];
__device__ int   g_cd[TT];

// output layout (float32): [x 57344][adj 262144][batch 8192]
#define OUT_X 0
#define OUT_ADJ 57344
#define OUT_BATCH 319488

// ==================== prep kernel ====================
__global__ void prep_kernel(
    const float* __restrict__ nf,
    const float* __restrict__ Wih_n, const float* __restrict__ Whh_n,
    const float* __restrict__ bih_n, const float* __restrict__ bhh_n,
    const float* __restrict__ Wih_g, const float* __restrict__ Whh_g,
    const float* __restrict__ bih_g, const float* __restrict__ bhh_g,
    const float* __restrict__ Ws1,
    float* __restrict__ out)
{
    long t = (long)blockIdx.x * blockDim.x + threadIdx.x;

    if (t < 262144) {   // g_Wc4: [q][k][256]
        int q = (int)(t >> 16), rem = (int)(t & 65535);
        int k = rem >> 8, lc = rem & 255;
        int g = lc >> 6, hc = q * 64 + (lc & 63);
        float v;
        if (g < 2)       v = Wih_n[(g*256 + hc) * 270 + 14 + k] + Whh_n[(g*256 + hc) * 256 + k];
        else if (g == 2) v = Wih_n[(512 + hc) * 270 + 14 + k];
        else             v = Whh_n[(512 + hc) * 256 + k];
        g_Wc4[t] = v; return;
    }
    t -= 262144;
    if (t < 196608) {   // g_Wgi4: [q][k][192]
        int q = (int)(t / 49152), rem = (int)(t % 49152);
        int k = rem / 192, lc = rem % 192;
        int g = lc / 64, hc = q * 64 + (lc % 64);
        g_Wgi4[t] = Wih_g[(g*256 + hc) * 256 + k]; return;
    }
    t -= 196608;
    if (t < 196608) {   // g_Wgh4
        int q = (int)(t / 49152), rem = (int)(t % 49152);
        int k = rem / 192, lc = rem % 192;
        int g = lc / 64, hc = q * 64 + (lc % 64);
        g_Wgh4[t] = Whh_g[(g*256 + hc) * 256 + k]; return;
    }
    t -= 196608;
    if (t < 1024) {     // g_bv4
        int q = (int)(t >> 8), lc = (int)(t & 255);
        int g = lc >> 6, hc = q * 64 + (lc & 63);
        float v;
        if (g < 2)       v = bih_n[g*256 + hc] + bhh_n[g*256 + hc];
        else if (g == 2) v = bih_n[512 + hc];
        else             v = bhh_n[512 + hc];
        g_bv4[t] = v; return;
    }
    t -= 1024;
    if (t < 768) {      // g_bgi4
        int q = (int)(t / 192), lc = (int)(t % 192);
        int g = lc / 64, hc = q * 64 + (lc % 64);
        g_bgi4[t] = bih_g[g*256 + hc]; return;
    }
    t -= 768;
    if (t < 768) {      // g_bgh4
        int q = (int)(t / 192), lc = (int)(t % 192);
        int g = lc / 64, hc = q * 64 + (lc % 64);
        g_bgh4[t] = bhh_g[g*256 + hc]; return;
    }
    t -= 768;
    if (t < 7168) {     // g_PQi4: [q][f][256]
        int q = (int)(t / 1792), rem = (int)(t % 1792);
        int f = rem / 256, lc = rem % 256;
        int g = lc >> 6, hc = q * 64 + (lc & 63);
        g_PQi4[t] = (g < 3) ? Wih_n[(g*256 + hc) * 270 + f] : 0.f; return;
    }
    t -= 7168;
    if (t < 7168) {     // g_PQj4
        int q = (int)(t / 1792), rem = (int)(t % 1792);
        int f = rem / 256, lc = rem % 256;
        int g = lc >> 6, hc = q * 64 + (lc & 63);
        g_PQj4[t] = (g < 3) ? Wih_n[(g*256 + hc) * 270 + 7 + f] : 0.f; return;
    }
    t -= 7168;
    if (t < 16384) {    // Ws1T [k][u]
        int k = (int)(t >> 6), u = (int)(t & 63);
        g_Ws1T[t] = Ws1[u * 256 + k]; return;
    }
    t -= 16384;
    if (t < BB * NN) {  // argmax one-hot
        const float* p = nf + t * FF;
        int best = 0;
        #pragma unroll
        for (int f = 0; f < FF; f++) if (p[f] > 0.5f) best = f;
        g_idx[t] = best; return;
    }
    t -= BB * NN;
    if (t < TT) {       // anti-diagonal placement
        int m = (int)t;
        int d = (int)((1.0 + sqrt(1.0 + 8.0 * (double)m)) * 0.5);
        while (d * (d - 1) / 2 > m) d--;
        while ((d + 1) * d / 2 <= m) d++;
        int rr = m - d * (d - 1) / 2;
        g_rd[m] = rr; g_cd[m] = rr + NN - d; return;
    }
    t -= TT;
    if (t < BB * NN * FF) { out[OUT_X + t] = nf[t]; return; }
    t -= BB * NN * FF;
    if (t < BB * NN * NN) { out[OUT_ADJ + t] = 0.f; return; }
    t -= BB * NN * NN;
    if (t < BB * NN) { out[OUT_BATCH + t] = (float)(t >> 5); return; }
}

// ==================== helpers ====================
__device__ __forceinline__ float sigm(float x) { return 1.f / (1.f + expf(-x)); }

__device__ __forceinline__ void ffma2(unsigned long long& d,
                                      unsigned long long a, unsigned long long b) {
    asm("fma.rn.f32x2 %0, %1, %2, %0;" : "+l"(d) : "l"(a), "l"(b));
}

__device__ __forceinline__ unsigned long long dup2(float w) {
    unsigned long long r;
    asm("mov.b64 %0, {%1, %1};" : "=l"(r) : "r"(__float_as_uint(w)));
    return r;
}

__device__ __forceinline__ float2 unpk(unsigned long long v) {
    float2 r;
    r.x = __uint_as_float((unsigned)(v & 0xffffffffu));
    r.y = __uint_as_float((unsigned)(v >> 32));
    return r;
}

__device__ __forceinline__ void st_peer64(float* p, unsigned peer, unsigned long long bits) {
    unsigned la = (unsigned)__cvta_generic_to_shared(p);
    unsigned ra;
    asm volatile("mapa.shared::cluster.u32 %0, %1, %2;" : "=r"(ra) : "r"(la), "r"(peer));
    asm volatile("st.shared::cluster.b64 [%0], %1;" :: "r"(ra), "l"(bits) : "memory");
}

#define CLUSTER_SYNC() do { \
    asm volatile("barrier.cluster.arrive.aligned;" ::: "memory"); \
    asm volatile("barrier.cluster.wait.aligned;" ::: "memory"); } while (0)

// node gemm: resident KRES from smem + tail from global with 16-deep reg prefetch.
// thread owns col lc; h layout [k][8 rows]; accs = 4 rowpair f32x2.
__device__ __forceinline__ void gemmN(const float* __restrict__ sW,
                                      const float* __restrict__ gWtail, // at k=KRES, stride LCN
                                      const float* __restrict__ hb, int lc,
                                      unsigned long long& a0, unsigned long long& a1,
                                      unsigned long long& a2, unsigned long long& a3)
{
    a0 = a1 = a2 = a3 = 0ull;
    const float* wp = sW + lc;
    #pragma unroll 8
    for (int k = 0; k < KRES; k++) {
        unsigned long long wd = dup2(wp[k * LCN]);
        ulonglong2 h01 = *(const ulonglong2*)(hb + k * 8);
        ulonglong2 h23 = *(const ulonglong2*)(hb + k * 8 + 4);
        ffma2(a0, wd, h01.x); ffma2(a1, wd, h01.y);
        ffma2(a2, wd, h23.x); ffma2(a3, wd, h23.y);
    }
    const float* gp = gWtail + lc;
    float wn[16];
    #pragma unroll
    for (int x = 0; x < 16; x++) wn[x] = gp[x * LCN];
    for (int blk = 0; blk < TAILB; blk++) {
        float wc[16];
        #pragma unroll
        for (int x = 0; x < 16; x++) wc[x] = wn[x];
        if (blk + 1 < TAILB) {
            const float* np = gp + (blk + 1) * 16 * LCN;
            #pragma unroll
            for (int x = 0; x < 16; x++) wn[x] = np[x * LCN];
        }
        const float* hkb = hb + (KRES + blk * 16) * 8;
        #pragma unroll
        for (int x = 0; x < 16; x++) {
            unsigned long long wd = dup2(wc[x]);
            ulonglong2 h01 = *(const ulonglong2*)(hkb + x * 8);
            ulonglong2 h23 = *(const ulonglong2*)(hkb + x * 8 + 4);
            ffma2(a0, wd, h01.x); ffma2(a1, wd, h01.y);
            ffma2(a2, wd, h23.x); ffma2(a3, wd, h23.y);
        }
    }
}

// graph gemm: all 256 k from global, stride LCG, 16-deep reg prefetch.
__device__ __forceinline__ void gemmG(const float* __restrict__ gW,
                                      const float* __restrict__ hb, int lc,
                                      unsigned long long& a0, unsigned long long& a1,
                                      unsigned long long& a2, unsigned long long& a3)
{
    a0 = a1 = a2 = a3 = 0ull;
    const float* gp = gW + lc;
    float wn[16];
    #pragma unroll
    for (int x = 0; x < 16; x++) wn[x] = gp[x * LCG];
    for (int blk = 0; blk < 16; blk++) {
        float wc[16];
        #pragma unroll
        for (int x = 0; x < 16; x++) wc[x] = wn[x];
        if (blk + 1 < 16) {
            const float* np = gp + (blk + 1) * 16 * LCG;
            #pragma unroll
            for (int x = 0; x < 16; x++) wn[x] = np[x * LCG];
        }
        const float* hkb = hb + blk * 16 * 8;
        #pragma unroll
        for (int x = 0; x < 16; x++) {
            unsigned long long wd = dup2(wc[x]);
            ulonglong2 h01 = *(const ulonglong2*)(hkb + x * 8);
            ulonglong2 h23 = *(const ulonglong2*)(hkb + x * 8 + 4);
            ffma2(a0, wd, h01.x); ffma2(a1, wd, h01.y);
            ffma2(a2, wd, h23.x); ffma2(a3, wd, h23.y);
        }
    }
}

// ---------------- smem layout (float offsets) ----------------
#define SO_WC   0                         // KRES*256 = 24576
#define SO_W1T  (SO_WC + KRES * LCN)      // 24576
#define SO_HA   (SO_W1T + 16384)          // 40960  node h buf A [k][8]
#define SO_HB   (SO_HA + 2048)            // 43008  node h buf B
#define SO_GA   (SO_HB + 2048)            // 45056  graph h buf A
#define SO_GB   (SO_GA + 2048)            // 47104  graph h buf B
#define SO_SG   (SO_GB + 2048)            // 49152  gate staging [r][256]
#define SO_SG2  (SO_SG + 2048)            // 51200  graph gh staging [r][256]
#define SO_PQI  (SO_SG2 + 2048)           // 53248  [f][256]
#define SO_PQJ  (SO_PQI + 1792)           // 55040
#define SO_IDX  (SO_PQJ + 1792)           // 56832  (256 ints)
#define SO_SP   (SO_IDX + 256)            // 57088  score partials [4]
#define SMEM_FLOATS (SO_SP + 8)           // 57096
#define SMEM_BYTES (SMEM_FLOATS * 4)      // 228384

// ==================== main chain kernel ====================
__global__ void __launch_bounds__(256, 1) __cluster_dims__(4, 1, 1)
chain_kernel(const float* __restrict__ z, const float* __restrict__ uin,
             const float* __restrict__ bs1, const float* __restrict__ Ws2,
             const float* __restrict__ bs2, float* __restrict__ out)
{
    extern __shared__ float sm[];
    float* sWc  = sm + SO_WC;
    float* sW1T = sm + SO_W1T;
    float* hBuf[2] = { sm + SO_HA, sm + SO_HB };
    float* gBuf[2] = { sm + SO_GA, sm + SO_GB };
    float* sg   = sm + SO_SG;
    float* sg2  = sm + SO_SG2;
    float* sPQi = sm + SO_PQI;
    float* sPQj = sm + SO_PQJ;
    int*   sidx = (int*)(sm + SO_IDX);
    float* spart = sm + SO_SP;

    const int t = threadIdx.x;
    const int q = blockIdx.x & 3;           // cluster rank
    const int cid = blockIdx.x >> 2;
    const int b0 = cid * RR;

    const float* WcG  = g_Wc4  + q * (HH * LCN);
    const float* WgiG = g_Wgi4 + q * (HH * LCG);
    const float* WghG = g_Wgh4 + q * (HH * LCG);

    // ---- init smem ----
    for (int x = t; x < KRES * LCN; x += 256) sWc[x] = WcG[x];
    for (int x = t; x < 16384; x += 256) sW1T[x] = g_Ws1T[x];
    for (int x = t; x < FF * LCN; x += 256) {
        sPQi[x] = g_PQi4[q * FF * LCN + x];
        sPQj[x] = g_PQj4[q * FF * LCN + x];
    }
    for (int x = t; x < 2048; x += 256) {       // graph h init [k][8]
        int k = x >> 3, r = x & 7;
        gBuf[0][x] = z[(b0 + r) * HH + k];
    }
    for (int x = t; x < RR * NN; x += 256) sidx[x] = g_idx[b0 * NN + x];

    // per-thread constants
    const float bvr  = g_bv4[q * LCN + t];                       // node bias (lc = t)
    const float bgir = (t < LCG) ? g_bgi4[q * LCG + t] : 0.f;
    const float bghr = (t < LCG) ? g_bgh4[q * LCG + t] : 0.f;
    const float b1r  = (t < 128) ? bs1[t & 63] : 0.f;
    const float w2r  = (t < 128) ? Ws2[t & 63] : 0.f;
    const float bs2v = *bs2;
    const int gsel = t >> 6;                    // gate group of this thread's col
    __syncthreads();
    CLUSTER_SYNC();

    const int hcl = t & 63;                     // activation h-col (local)
    const int p   = t >> 6;                     // activation rowpair 0..3
    const int hc  = q * 64 + hcl;               // global h-col owned

    int pb = 0, gpb = 0;

    for (int i = 0; i < NN - 1; i++) {
        // node_h := graph_h (local full copy)
        pb = 0;
        {
            const float* gs = gBuf[gpb];
            float* d = hBuf[0];
            for (int x = t; x < 2048; x += 256) d[x] = gs[x];
        }
        __syncthreads();

        int fi[RR];
        #pragma unroll
        for (int r = 0; r < RR; r++) fi[r] = sidx[r * NN + i];

        for (int j = i + 1; j < NN; j++) {
            float* hR = hBuf[pb];
            float* hW = hBuf[pb ^ 1];

            unsigned long long a0, a1, a2, a3;
            gemmN(sWc, WcG + KRES * LCN, hR, t, a0, a1, a2, a3);

            // stage gates: sg[r][t] = acc + bias (+ one-hot gathers for g<3)
            {
                float2 v01 = unpk(a0), v23 = unpk(a1), v45 = unpk(a2), v67 = unpk(a3);
                float v[RR] = { v01.x, v01.y, v23.x, v23.y, v45.x, v45.y, v67.x, v67.y };
                if (gsel < 3) {
                    #pragma unroll
                    for (int r = 0; r < RR; r++) {
                        int fj = sidx[r * NN + j];
                        v[r] += bvr + sPQi[fi[r] * LCN + t] + sPQj[fj * LCN + t];
                    }
                } else {
                    #pragma unroll
                    for (int r = 0; r < RR; r++) v[r] += bvr;
                }
                #pragma unroll
                for (int r = 0; r < RR; r++) sg[r * LCN + t] = v[r];
            }
            __syncthreads();

            // GRU activation: thread (hcl, p) -> rows 2p, 2p+1 of col hc
            {
                float hv[2];
                #pragma unroll
                for (int s = 0; s < 2; s++) {
                    int r = 2 * p + s;
                    float gr = sigm(sg[r * LCN + hcl]);
                    float gz = sigm(sg[r * LCN + 64 + hcl]);
                    float gn = tanhf(sg[r * LCN + 128 + hcl] + gr * sg[r * LCN + 192 + hcl]);
                    float ho = hR[hc * 8 + r];
                    hv[s] = (1.f - gz) * gn + gz * ho;
                }
                unsigned long long bits =
                    ((unsigned long long)__float_as_uint(hv[1]) << 32)
                    | (unsigned long long)__float_as_uint(hv[0]);
                float* dp = hW + hc * 8 + 2 * p;
                *(unsigned long long*)dp = bits;
                #pragma unroll
                for (int pr = 0; pr < 4; pr++)
                    if (pr != q) st_peer64(dp, (unsigned)pr, bits);
            }
            CLUSTER_SYNC();

            // score head: this CTA finalizes rows 2q, 2q+1
            if (t < 128) {
                const int rl = t >> 6;              // 0/1
                const int u = t & 63;
                const int rg = 2 * q + rl;
                const float* hp = hW + rg;          // stride 8
                const float* wp = sW1T + u;         // stride 64
                float c0 = 0.f, c1 = 0.f, c2 = 0.f, c3 = 0.f;
                #pragma unroll 8
                for (int k = 0; k < HH; k += 4) {
                    c0 = fmaf(wp[k * 64],       hp[k * 8],       c0);
                    c1 = fmaf(wp[(k + 1) * 64], hp[(k + 1) * 8], c1);
                    c2 = fmaf(wp[(k + 2) * 64], hp[(k + 2) * 8], c2);
                    c3 = fmaf(wp[(k + 3) * 64], hp[(k + 3) * 8], c3);
                }
                float hid = fmaxf(c0 + c1 + c2 + c3 + b1r, 0.f);
                float sp = hid * w2r;
                #pragma unroll
                for (int o = 16; o; o >>= 1) sp += __shfl_down_sync(0xffffffffu, sp, o);
                if ((t & 31) == 0) spart[t >> 5] = sp;
                asm volatile("bar.sync 1, 128;" ::: "memory");
                if (t < 2) {
                    float s = spart[2 * t] + spart[2 * t + 1] + bs2v;
                    float prob = sigm(s);
                    int m = i * (NN - 1) - (i * (i - 1)) / 2 + (j - i - 1);
                    int b = b0 + 2 * q + t;
                    float uu = uin[b * TT + m];
                    float pc = fminf(fmaxf(prob, EPSF), 1.f - EPSF);
                    float e;
                    if (pc < 0.499f || pc > 0.501f) {
                        e = (log1pf(-pc + uu * (2.f * pc - 1.f)) - log1pf(-pc))
                          / (logf(pc) - log1pf(-pc));
                    } else {
                        e = uu;
                    }
                    int rr = g_rd[m], cc = g_cd[m];
                    float* adj = out + OUT_ADJ + b * (NN * NN);
                    adj[rr * NN + cc] = e;
                    adj[cc * NN + rr] = e;
                }
            }
            pb ^= 1;
        }

        // graph GRU (result of last i unused -> skip)
        if (i < NN - 2) {
            const float* hfin = hBuf[pb];
            const float* ghR = gBuf[gpb];
            float* ghW = gBuf[gpb ^ 1];

            if (t < LCG) {
                unsigned long long a0, a1, a2, a3;
                gemmG(WgiG, hfin, t, a0, a1, a2, a3);
                {
                    float2 v01 = unpk(a0), v23 = unpk(a1), v45 = unpk(a2), v67 = unpk(a3);
                    float v[RR] = { v01.x, v01.y, v23.x, v23.y, v45.x, v45.y, v67.x, v67.y };
                    #pragma unroll
                    for (int r = 0; r < RR; r++) sg[r * LCN + t] = v[r] + bgir;
                }
                gemmG(WghG, ghR, t, a0, a1, a2, a3);
                {
                    float2 v01 = unpk(a0), v23 = unpk(a1), v45 = unpk(a2), v67 = unpk(a3);
                    float v[RR] = { v01.x, v01.y, v23.x, v23.y, v45.x, v45.y, v67.x, v67.y };
                    #pragma unroll
                    for (int r = 0; r < RR; r++) sg2[r * LCN + t] = v[r] + bghr;
                }
            }
            __syncthreads();

            {
                float hv[2];
                #pragma unroll
                for (int s = 0; s < 2; s++) {
                    int r = 2 * p + s;
                    float rr = sigm(sg[r * LCN + hcl] + sg2[r * LCN + hcl]);
                    float zz = sigm(sg[r * LCN + 64 + hcl] + sg2[r * LCN + 64 + hcl]);
                    float nn = tanhf(sg[r * LCN + 128 + hcl]
                                   + rr * sg2[r * LCN + 128 + hcl]);
                    float go = ghR[hc * 8 + r];
                    hv[s] = (1.f - zz) * nn + zz * go;
                }
                unsigned long long bits =
                    ((unsigned long long)__float_as_uint(hv[1]) << 32)
                    | (unsigned long long)__float_as_uint(hv[0]);
                float* dp = ghW + hc * 8 + 2 * p;
                *(unsigned long long*)dp = bits;
                #pragma unroll
                for (int pr = 0; pr < 4; pr++)
                    if (pr != q) st_peer64(dp, (unsigned)pr, bits);
            }
            CLUSTER_SYNC();
            gpb ^= 1;
        }
    }
}

// ==================== launch ====================
extern "C" void kernel_launch(void* const* d_in, const int* in_sizes, int n_in,
                              void* d_out, int out_size)
{
    const float* z     = (const float*)d_in[0];
    const float* nf    = (const float*)d_in[1];
    const float* u     = (const float*)d_in[2];
    const float* Wih_n = (const float*)d_in[3];
    const float* Whh_n = (const float*)d_in[4];
    const float* bih_n = (const float*)d_in[5];
    const float* bhh_n = (const float*)d_in[6];
    const float* Wih_g = (const float*)d_in[7];
    const float* Whh_g = (const float*)d_in[8];
    const float* bih_g = (const float*)d_in[9];
    const float* bhh_g = (const float*)d_in[10];
    const float* Ws1   = (const float*)d_in[11];
    const float* bs1   = (const float*)d_in[12];
    const float* Ws2   = (const float*)d_in[13];
    const float* bs2   = (const float*)d_in[14];
    float* out = (float*)d_out;

    const long total = 262144L + 196608L * 2 + 1024 + 768 * 2 + 7168 * 2 + 16384
                     + BB * NN + TT + BB * NN * FF + BB * NN * NN + BB * NN;
    int blocks = (int)((total + 255) / 256);
    prep_kernel<<<blocks, 256>>>(nf, Wih_n, Whh_n, bih_n, bhh_n,
                                 Wih_g, Whh_g, bih_g, bhh_g, Ws1, out);

    cudaFuncSetAttribute(chain_kernel,
                         cudaFuncAttributeMaxDynamicSharedMemorySize, SMEM_BYTES);
    chain_kernel<<<NCTA, 256, SMEM_BYTES>>>(z, u, bs1, Ws2, bs2, out);
}

// round 7
// speedup vs baseline: 1.8447x; 1.6052x over previous
#include <cuda_runtime.h>
#include <math.h>

// ---------------- problem constants ----------------
#define BB 256
#define NN 32
#define HH 256
#define FF 7
#define TT 496
#define RR 8                 // batch rows per 4-CTA cluster
#define NCLUST (BB / RR)     // 32 clusters
#define NCTA (NCLUST * 4)    // 128 CTAs
#define LCN 256              // node gemm local cols per CTA
#define LCG 192              // graph gemm local cols per matrix
#define NT 512               // threads per CTA
#define KQ 64                // k per quarter (4-way K split)
#define EPSF 1.1920929e-07f

typedef unsigned long long ull;

// ---------------- device scratch ----------------
__device__ float g_Wc4[4 * HH * LCN];    // node combined weights [q][k][lc]
__device__ float g_Wgi4[4 * HH * LCG];   // graph Wih slice [q][k][lc]
__device__ float g_Wgh4[4 * HH * LCG];   // graph Whh slice
__device__ float g_bv4[4 * LCN];         // node combined bias [q][lc]
__device__ float g_bgi4[4 * LCG];        // graph ih bias
__device__ float g_bgh4[4 * LCG];        // graph hh bias
__device__ float g_PQi4[4 * FF * LCN];   // one-hot(i) gathers [q][f][lc] (g3=0)
__device__ float g_PQj4[4 * FF * LCN];
__device__ float g_Ws1T[HH * 64];        // Ws1 transposed [k][u]
__device__ int   g_idx[BB * NN];
__device__ int   g_rd[TT];
__device__ int   g_cd[TT];

// output layout (float32): [x 57344][adj 262144][batch 8192]
#define OUT_X 0
#define OUT_ADJ 57344
#define OUT_BATCH 319488

// ==================== prep kernel (unchanged from R6) ====================
__global__ void prep_kernel(
    const float* __restrict__ nf,
    const float* __restrict__ Wih_n, const float* __restrict__ Whh_n,
    const float* __restrict__ bih_n, const float* __restrict__ bhh_n,
    const float* __restrict__ Wih_g, const float* __restrict__ Whh_g,
    const float* __restrict__ bih_g, const float* __restrict__ bhh_g,
    const float* __restrict__ Ws1,
    float* __restrict__ out)
{
    long t = (long)blockIdx.x * blockDim.x + threadIdx.x;

    if (t < 262144) {   // g_Wc4: [q][k][256]
        int q = (int)(t >> 16), rem = (int)(t & 65535);
        int k = rem >> 8, lc = rem & 255;
        int g = lc >> 6, hc = q * 64 + (lc & 63);
        float v;
        if (g < 2)       v = Wih_n[(g*256 + hc) * 270 + 14 + k] + Whh_n[(g*256 + hc) * 256 + k];
        else if (g == 2) v = Wih_n[(512 + hc) * 270 + 14 + k];
        else             v = Whh_n[(512 + hc) * 256 + k];
        g_Wc4[t] = v; return;
    }
    t -= 262144;
    if (t < 196608) {   // g_Wgi4: [q][k][192]
        int q = (int)(t / 49152), rem = (int)(t % 49152);
        int k = rem / 192, lc = rem % 192;
        int g = lc / 64, hc = q * 64 + (lc % 64);
        g_Wgi4[t] = Wih_g[(g*256 + hc) * 256 + k]; return;
    }
    t -= 196608;
    if (t < 196608) {   // g_Wgh4
        int q = (int)(t / 49152), rem = (int)(t % 49152);
        int k = rem / 192, lc = rem % 192;
        int g = lc / 64, hc = q * 64 + (lc % 64);
        g_Wgh4[t] = Whh_g[(g*256 + hc) * 256 + k]; return;
    }
    t -= 196608;
    if (t < 1024) {     // g_bv4
        int q = (int)(t >> 8), lc = (int)(t & 255);
        int g = lc >> 6, hc = q * 64 + (lc & 63);
        float v;
        if (g < 2)       v = bih_n[g*256 + hc] + bhh_n[g*256 + hc];
        else if (g == 2) v = bih_n[512 + hc];
        else             v = bhh_n[512 + hc];
        g_bv4[t] = v; return;
    }
    t -= 1024;
    if (t < 768) {      // g_bgi4
        int q = (int)(t / 192), lc = (int)(t % 192);
        int g = lc / 64, hc = q * 64 + (lc % 64);
        g_bgi4[t] = bih_g[g*256 + hc]; return;
    }
    t -= 768;
    if (t < 768) {      // g_bgh4
        int q = (int)(t / 192), lc = (int)(t % 192);
        int g = lc / 64, hc = q * 64 + (lc % 64);
        g_bgh4[t] = bhh_g[g*256 + hc]; return;
    }
    t -= 768;
    if (t < 7168) {     // g_PQi4: [q][f][256]
        int q = (int)(t / 1792), rem = (int)(t % 1792);
        int f = rem / 256, lc = rem % 256;
        int g = lc >> 6, hc = q * 64 + (lc & 63);
        g_PQi4[t] = (g < 3) ? Wih_n[(g*256 + hc) * 270 + f] : 0.f; return;
    }
    t -= 7168;
    if (t < 7168) {     // g_PQj4
        int q = (int)(t / 1792), rem = (int)(t % 1792);
        int f = rem / 256, lc = rem % 256;
        int g = lc >> 6, hc = q * 64 + (lc & 63);
        g_PQj4[t] = (g < 3) ? Wih_n[(g*256 + hc) * 270 + 7 + f] : 0.f; return;
    }
    t -= 7168;
    if (t < 16384) {    // Ws1T [k][u]
        int k = (int)(t >> 6), u = (int)(t & 63);
        g_Ws1T[t] = Ws1[u * 256 + k]; return;
    }
    t -= 16384;
    if (t < BB * NN) {  // argmax one-hot
        const float* p = nf + t * FF;
        int best = 0;
        #pragma unroll
        for (int f = 0; f < FF; f++) if (p[f] > 0.5f) best = f;
        g_idx[t] = best; return;
    }
    t -= BB * NN;
    if (t < TT) {       // anti-diagonal placement
        int m = (int)t;
        int d = (int)((1.0 + sqrt(1.0 + 8.0 * (double)m)) * 0.5);
        while (d * (d - 1) / 2 > m) d--;
        while ((d + 1) * d / 2 <= m) d++;
        int rr = m - d * (d - 1) / 2;
        g_rd[m] = rr; g_cd[m] = rr + NN - d; return;
    }
    t -= TT;
    if (t < BB * NN * FF) { out[OUT_X + t] = nf[t]; return; }
    t -= BB * NN * FF;
    if (t < BB * NN * NN) { out[OUT_ADJ + t] = 0.f; return; }
    t -= BB * NN * NN;
    if (t < BB * NN) { out[OUT_BATCH + t] = (float)(t >> 5); return; }
}

// ==================== helpers ====================
__device__ __forceinline__ float sigm(float x) { return 1.f / (1.f + expf(-x)); }

__device__ __forceinline__ void ffma2(ull& d, ull a, ull b) {
    asm("fma.rn.f32x2 %0, %1, %2, %0;" : "+l"(d) : "l"(a), "l"(b));
}
__device__ __forceinline__ void fadd2(ull& d, ull a) {
    asm("add.rn.f32x2 %0, %0, %1;" : "+l"(d) : "l"(a));
}
__device__ __forceinline__ ull dup2(float w) {
    ull r;
    asm("mov.b64 %0, {%1, %1};" : "=l"(r) : "r"(__float_as_uint(w)));
    return r;
}
__device__ __forceinline__ float2 unpk(ull v) {
    float2 r;
    r.x = __uint_as_float((unsigned)(v & 0xffffffffu));
    r.y = __uint_as_float((unsigned)(v >> 32));
    return r;
}
__device__ __forceinline__ void st_peer64(float* p, unsigned peer, ull bits) {
    unsigned la = (unsigned)__cvta_generic_to_shared(p);
    unsigned ra;
    asm volatile("mapa.shared::cluster.u32 %0, %1, %2;" : "=r"(ra) : "r"(la), "r"(peer));
    asm volatile("st.shared::cluster.b64 [%0], %1;" :: "r"(ra), "l"(bits) : "memory");
}
#define CLUSTER_SYNC() do { \
    asm volatile("barrier.cluster.arrive.aligned;" ::: "memory"); \
    asm volatile("barrier.cluster.wait.aligned;" ::: "memory"); } while (0)

// ---- quarter GEMM bodies: 2 cols/thread, 64 k, 8 rows ----
// acc layout: aA[0..3], aB[0..3] = rowpairs for col a / col b
struct Acc8 { ull aA[4]; ull aB[4]; };

__device__ __forceinline__ void qgemm_smem(const float* __restrict__ sW, int c2,
                                           const float* __restrict__ hb, Acc8& A)
{
    const float2* wp = (const float2*)sW + c2;   // row stride LCN/2 float2
    #pragma unroll 8
    for (int k = 0; k < KQ; k++) {
        float2 w = wp[k * (LCN / 2)];
        ull wa = dup2(w.x), wb = dup2(w.y);
        ulonglong2 h01 = *(const ulonglong2*)(hb + k * 8);
        ulonglong2 h23 = *(const ulonglong2*)(hb + k * 8 + 4);
        ffma2(A.aA[0], wa, h01.x); ffma2(A.aA[1], wa, h01.y);
        ffma2(A.aA[2], wa, h23.x); ffma2(A.aA[3], wa, h23.y);
        ffma2(A.aB[0], wb, h01.x); ffma2(A.aB[1], wb, h01.y);
        ffma2(A.aB[2], wb, h23.x); ffma2(A.aB[3], wb, h23.y);
    }
}

template <int STRIDE2>  // row stride in float2 units
__device__ __forceinline__ void qgemm_glob(const float* __restrict__ gW, int c2,
                                           const float* __restrict__ hb, Acc8& A)
{
    const float2* gp = (const float2*)gW + c2;
    float2 wn[8];
    #pragma unroll
    for (int x = 0; x < 8; x++) wn[x] = gp[x * STRIDE2];
    #pragma unroll
    for (int blk = 0; blk < KQ / 8; blk++) {
        float2 wc[8];
        #pragma unroll
        for (int x = 0; x < 8; x++) wc[x] = wn[x];
        if (blk + 1 < KQ / 8) {
            const float2* np = gp + (blk + 1) * 8 * STRIDE2;
            #pragma unroll
            for (int x = 0; x < 8; x++) wn[x] = np[x * STRIDE2];
        }
        const float* hkb = hb + blk * 8 * 8;
        #pragma unroll
        for (int x = 0; x < 8; x++) {
            ull wa = dup2(wc[x].x), wb = dup2(wc[x].y);
            ulonglong2 h01 = *(const ulonglong2*)(hkb + x * 8);
            ulonglong2 h23 = *(const ulonglong2*)(hkb + x * 8 + 4);
            ffma2(A.aA[0], wa, h01.x); ffma2(A.aA[1], wa, h01.y);
            ffma2(A.aA[2], wa, h23.x); ffma2(A.aA[3], wa, h23.y);
            ffma2(A.aB[0], wb, h01.x); ffma2(A.aB[1], wb, h01.y);
            ffma2(A.aB[2], wb, h23.x); ffma2(A.aB[3], wb, h23.y);
        }
    }
}

// ---------------- smem layout (float offsets, all 16B-aligned) ----------------
#define SO_WC   0                          // 64*256 = 16384 (node quarter-0 weights)
#define SO_W1T  (SO_WC + KQ * LCN)         // 16384
#define SO_HA   (SO_W1T + 16384)           // 32768
#define SO_HB   (SO_HA + 2048)             // 34816
#define SO_GA   (SO_HB + 2048)             // 36864
#define SO_GB   (SO_GA + 2048)             // 38912
#define SO_SG   (SO_GB + 2048)             // 40960  [r][256]
#define SO_SG2  (SO_SG + 2048)             // 43008
#define SO_RED  (SO_SG2 + 2048)            // 45056  3*128*16 = 6144
#define SO_PQI  (SO_RED + 6144)            // 51200  [f][256]
#define SO_PQJ  (SO_PQI + 1792)            // 52992
#define SO_BGI  (SO_PQJ + 1792)            // 54784  192
#define SO_BGH  (SO_BGI + 192)             // 54976  192
#define SO_SPS  (SO_BGH + 192)             // 55168  score partials 3*128
#define SO_SP4  (SO_SPS + 384)             // 55552  4 warp partials (+pad)
#define SO_IDX  (SO_SP4 + 8)               // 55560  256 ints
#define SMEM_FLOATS (SO_IDX + 256)         // 55816
#define SMEM_BYTES (SMEM_FLOATS * 4)       // 223264

// ==================== main chain kernel ====================
__global__ void __launch_bounds__(NT, 1) __cluster_dims__(4, 1, 1)
chain_kernel(const float* __restrict__ z, const float* __restrict__ uin,
             const float* __restrict__ bs1, const float* __restrict__ Ws2,
             const float* __restrict__ bs2, float* __restrict__ out)
{
    extern __shared__ float sm[];
    float* sWc  = sm + SO_WC;
    float* sW1T = sm + SO_W1T;
    float* hBuf[2] = { sm + SO_HA, sm + SO_HB };
    float* gBuf[2] = { sm + SO_GA, sm + SO_GB };
    float* sg   = sm + SO_SG;
    float* sg2  = sm + SO_SG2;
    float* sred = sm + SO_RED;
    float* sPQi = sm + SO_PQI;
    float* sPQj = sm + SO_PQJ;
    float* sbgi = sm + SO_BGI;
    float* sbgh = sm + SO_BGH;
    float* sps  = sm + SO_SPS;
    float* sp4  = sm + SO_SP4;
    int*   sidx = (int*)(sm + SO_IDX);

    const int t = threadIdx.x;
    const int q = blockIdx.x & 3;
    const int cid = blockIdx.x >> 2;
    const int b0 = cid * RR;

    const float* WcG  = g_Wc4  + q * (HH * LCN);
    const float* WgiG = g_Wgi4 + q * (HH * LCG);
    const float* WghG = g_Wgh4 + q * (HH * LCG);

    // ---- init smem ----
    for (int x = t; x < KQ * LCN; x += NT) sWc[x] = WcG[x];      // quarter-0 resident
    for (int x = t; x < 16384; x += NT) sW1T[x] = g_Ws1T[x];
    for (int x = t; x < FF * LCN; x += NT) {
        sPQi[x] = g_PQi4[q * FF * LCN + x];
        sPQj[x] = g_PQj4[q * FF * LCN + x];
    }
    for (int x = t; x < 2048; x += NT) {      // graph h init [k][8]
        int k = x >> 3, r = x & 7;
        gBuf[0][x] = z[(b0 + r) * HH + k];
    }
    for (int x = t; x < LCG; x += NT) { sbgi[x] = g_bgi4[q*LCG + x]; sbgh[x] = g_bgh4[q*LCG + x]; }
    if (t < RR * NN) sidx[t] = g_idx[b0 * NN + t];

    // per-thread role constants
    const int c2 = t & 127;               // col-pair 0..127
    const int kq = t >> 7;                // k-quarter 0..3
    const int lc0 = 2 * c2;
    const float bvx = (kq == 0) ? g_bv4[q*LCN + lc0]     : 0.f;
    const float bvy = (kq == 0) ? g_bv4[q*LCN + lc0 + 1] : 0.f;
    const float b1r  = (t < 128) ? bs1[t & 63] : 0.f;
    const float w2r  = (t < 128) ? Ws2[t & 63] : 0.f;
    const float bs2v = *bs2;
    __syncthreads();
    CLUSTER_SYNC();

    // activation mapping (t < 256): col hcl, rowpair p
    const int hcl = t & 63;
    const int p   = (t >> 6) & 3;
    const int hc  = q * 64 + hcl;
    // score mapping
    const int su  = t & 63;               // hidden unit
    const int srow = (t >> 6) & 1;        // local row 0/1
    const int skq = t >> 7;               // k quarter
    // graph gemm mapping (t < 384)
    const int gc2 = t % 96;
    const int gkq = t / 96;

    int pb = 0, gpb = 0;

    for (int i = 0; i < NN - 1; i++) {
        pb = 0;
        {
            const float* gs = gBuf[gpb];
            float* d = hBuf[0];
            for (int x = t; x < 2048; x += NT) d[x] = gs[x];
        }
        __syncthreads();

        int fi[RR];
        if (t < 128) {
            #pragma unroll
            for (int r = 0; r < RR; r++) fi[r] = sidx[r * NN + i];
        }

        for (int j = i + 1; j < NN; j++) {
            float* hR = hBuf[pb];
            float* hW = hBuf[pb ^ 1];

            // ---- K-split node gemm ----
            Acc8 A;
            #pragma unroll
            for (int x = 0; x < 4; x++) { A.aA[x] = 0ull; A.aB[x] = 0ull; }
            if (kq == 0) qgemm_smem(sWc, c2, hR, A);
            else qgemm_glob<LCN/2>(WcG + kq * KQ * LCN, c2, hR + kq * KQ * 8, A);

            if (kq > 0) {   // write partials (16 floats = 4 STS.128)
                ulonglong2* rp = (ulonglong2*)(sred + ((kq - 1) * 128 + c2) * 16);
                rp[0] = make_ulonglong2(A.aA[0], A.aA[1]);
                rp[1] = make_ulonglong2(A.aA[2], A.aA[3]);
                rp[2] = make_ulonglong2(A.aB[0], A.aB[1]);
                rp[3] = make_ulonglong2(A.aB[2], A.aB[3]);
            }
            __syncthreads();

            if (t < 128) {  // reduce 4 partials + bias + one-hot, write sg
                #pragma unroll
                for (int s = 0; s < 3; s++) {
                    const ulonglong2* rp = (const ulonglong2*)(sred + (s * 128 + c2) * 16);
                    ulonglong2 r0 = rp[0], r1 = rp[1], r2 = rp[2], r3 = rp[3];
                    fadd2(A.aA[0], r0.x); fadd2(A.aA[1], r0.y);
                    fadd2(A.aA[2], r1.x); fadd2(A.aA[3], r1.y);
                    fadd2(A.aB[0], r2.x); fadd2(A.aB[1], r2.y);
                    fadd2(A.aB[2], r3.x); fadd2(A.aB[3], r3.y);
                }
                float va[RR], vb[RR];
                #pragma unroll
                for (int x = 0; x < 4; x++) {
                    float2 fa = unpk(A.aA[x]), fb = unpk(A.aB[x]);
                    va[2*x] = fa.x; va[2*x+1] = fa.y;
                    vb[2*x] = fb.x; vb[2*x+1] = fb.y;
                }
                if (t < 96) {   // gates r/z/n_i get one-hot gathers
                    #pragma unroll
                    for (int r = 0; r < RR; r++) {
                        int fj = sidx[r * NN + j];
                        va[r] += bvx + sPQi[fi[r]*LCN + lc0]   + sPQj[fj*LCN + lc0];
                        vb[r] += bvy + sPQi[fi[r]*LCN + lc0+1] + sPQj[fj*LCN + lc0+1];
                    }
                } else {
                    #pragma unroll
                    for (int r = 0; r < RR; r++) { va[r] += bvx; vb[r] += bvy; }
                }
                #pragma unroll
                for (int r = 0; r < RR; r++) {
                    ull bits = ((ull)__float_as_uint(vb[r]) << 32)
                             | (ull)__float_as_uint(va[r]);
                    *(ull*)(sg + r * LCN + lc0) = bits;
                }
            }
            __syncthreads();

            // ---- GRU activation (t < 256): rows 2p,2p+1 of col hc ----
            if (t < 256) {
                float hv[2];
                #pragma unroll
                for (int s = 0; s < 2; s++) {
                    int r = 2 * p + s;
                    float gr = sigm(sg[r * LCN + hcl]);
                    float gz = sigm(sg[r * LCN + 64 + hcl]);
                    float gn = tanhf(sg[r * LCN + 128 + hcl] + gr * sg[r * LCN + 192 + hcl]);
                    float ho = hR[hc * 8 + r];
                    hv[s] = (1.f - gz) * gn + gz * ho;
                }
                ull bits = ((ull)__float_as_uint(hv[1]) << 32)
                         | (ull)__float_as_uint(hv[0]);
                float* dp = hW + hc * 8 + 2 * p;
                *(ull*)dp = bits;
                #pragma unroll
                for (int pr = 0; pr < 4; pr++)
                    if (pr != q) st_peer64(dp, (unsigned)pr, bits);
            }
            CLUSTER_SYNC();

            // ---- K-split score head: rows 2q,2q+1 ----
            {
                const int rg = 2 * q + srow;
                const float* hp = hW + rg + skq * KQ * 8;
                const float* wp = sW1T + su + skq * KQ * 64;
                float c0 = 0.f, c1 = 0.f;
                #pragma unroll 8
                for (int k = 0; k < KQ; k += 2) {
                    c0 = fmaf(wp[k * 64],       hp[k * 8],       c0);
                    c1 = fmaf(wp[(k + 1) * 64], hp[(k + 1) * 8], c1);
                }
                float pv = c0 + c1;
                if (skq > 0) sps[(skq - 1) * 128 + (t & 127)] = pv;
                __syncthreads();
                if (t < 128) {
                    float hid = fmaxf(pv + sps[t] + sps[128 + t] + sps[256 + t] + b1r, 0.f);
                    float sp = hid * w2r;
                    #pragma unroll
                    for (int o = 16; o; o >>= 1) sp += __shfl_down_sync(0xffffffffu, sp, o);
                    if ((t & 31) == 0) sp4[t >> 5] = sp;
                    asm volatile("bar.sync 1, 128;" ::: "memory");
                    if (t < 2) {
                        float s = sp4[2 * t] + sp4[2 * t + 1] + bs2v;
                        float prob = sigm(s);
                        int m = i * (NN - 1) - (i * (i - 1)) / 2 + (j - i - 1);
                        int b = b0 + 2 * q + t;
                        float uu = uin[b * TT + m];
                        float pc = fminf(fmaxf(prob, EPSF), 1.f - EPSF);
                        float e;
                        if (pc < 0.499f || pc > 0.501f) {
                            e = (log1pf(-pc + uu * (2.f * pc - 1.f)) - log1pf(-pc))
                              / (logf(pc) - log1pf(-pc));
                        } else {
                            e = uu;
                        }
                        int rr = g_rd[m], cc = g_cd[m];
                        float* adj = out + OUT_ADJ + b * (NN * NN);
                        adj[rr * NN + cc] = e;
                        adj[cc * NN + rr] = e;
                    }
                }
            }
            pb ^= 1;
        }

        // ---- graph GRU (skip last unused) ----
        if (i < NN - 2) {
            const float* hfin = hBuf[pb];
            const float* ghR = gBuf[gpb];
            float* ghW = gBuf[gpb ^ 1];

            // pass 1: gi = Wgi @ hfin
            Acc8 A;
            #pragma unroll
            for (int x = 0; x < 4; x++) { A.aA[x] = 0ull; A.aB[x] = 0ull; }
            if (t < 384)
                qgemm_glob<LCG/2>(WgiG + gkq * KQ * LCG, gc2, hfin + gkq * KQ * 8, A);
            if (t >= 96 && t < 384) {
                ulonglong2* rp = (ulonglong2*)(sred + ((gkq - 1) * 128 + gc2) * 16);
                rp[0] = make_ulonglong2(A.aA[0], A.aA[1]);
                rp[1] = make_ulonglong2(A.aA[2], A.aA[3]);
                rp[2] = make_ulonglong2(A.aB[0], A.aB[1]);
                rp[3] = make_ulonglong2(A.aB[2], A.aB[3]);
            }
            __syncthreads();
            if (t < 96) {
                #pragma unroll
                for (int s = 0; s < 3; s++) {
                    const ulonglong2* rp = (const ulonglong2*)(sred + (s * 128 + gc2) * 16);
                    ulonglong2 r0 = rp[0], r1 = rp[1], r2 = rp[2], r3 = rp[3];
                    fadd2(A.aA[0], r0.x); fadd2(A.aA[1], r0.y);
                    fadd2(A.aA[2], r1.x); fadd2(A.aA[3], r1.y);
                    fadd2(A.aB[0], r2.x); fadd2(A.aB[1], r2.y);
                    fadd2(A.aB[2], r3.x); fadd2(A.aB[3], r3.y);
                }
                int glc = 2 * gc2;
                float bx = sbgi[glc], by = sbgi[glc + 1];
                #pragma unroll
                for (int x = 0; x < 4; x++) {
                    float2 fa = unpk(A.aA[x]), fb = unpk(A.aB[x]);
                    ull b0v = ((ull)__float_as_uint(fb.x + by) << 32) | (ull)__float_as_uint(fa.x + bx);
                    ull b1v = ((ull)__float_as_uint(fb.y + by) << 32) | (ull)__float_as_uint(fa.y + bx);
                    *(ull*)(sg + (2*x)   * LCN + glc) = b0v;
                    *(ull*)(sg + (2*x+1) * LCN + glc) = b1v;
                }
            }
            __syncthreads();

            // pass 2: gh = Wgh @ ghR
            #pragma unroll
            for (int x = 0; x < 4; x++) { A.aA[x] = 0ull; A.aB[x] = 0ull; }
            if (t < 384)
                qgemm_glob<LCG/2>(WghG + gkq * KQ * LCG, gc2, ghR + gkq * KQ * 8, A);
            if (t >= 96 && t < 384) {
                ulonglong2* rp = (ulonglong2*)(sred + ((gkq - 1) * 128 + gc2) * 16);
                rp[0] = make_ulonglong2(A.aA[0], A.aA[1]);
                rp[1] = make_ulonglong2(A.aA[2], A.aA[3]);
                rp[2] = make_ulonglong2(A.aB[0], A.aB[1]);
                rp[3] = make_ulonglong2(A.aB[2], A.aB[3]);
            }
            __syncthreads();
            if (t < 96) {
                #pragma unroll
                for (int s = 0; s < 3; s++) {
                    const ulonglong2* rp = (const ulonglong2*)(sred + (s * 128 + gc2) * 16);
                    ulonglong2 r0 = rp[0], r1 = rp[1], r2 = rp[2], r3 = rp[3];
                    fadd2(A.aA[0], r0.x); fadd2(A.aA[1], r0.y);
                    fadd2(A.aA[2], r1.x); fadd2(A.aA[3], r1.y);
                    fadd2(A.aB[0], r2.x); fadd2(A.aB[1], r2.y);
                    fadd2(A.aB[2], r3.x); fadd2(A.aB[3], r3.y);
                }
                int glc = 2 * gc2;
                float bx = sbgh[glc], by = sbgh[glc + 1];
                #pragma unroll
                for (int x = 0; x < 4; x++) {
                    float2 fa = unpk(A.aA[x]), fb = unpk(A.aB[x]);
                    ull b0v = ((ull)__float_as_uint(fb.x + by) << 32) | (ull)__float_as_uint(fa.x + bx);
                    ull b1v = ((ull)__float_as_uint(fb.y + by) << 32) | (ull)__float_as_uint(fa.y + bx);
                    *(ull*)(sg2 + (2*x)   * LCN + glc) = b0v;
                    *(ull*)(sg2 + (2*x+1) * LCN + glc) = b1v;
                }
            }
            __syncthreads();

            if (t < 256) {
                float hv[2];
                #pragma unroll
                for (int s = 0; s < 2; s++) {
                    int r = 2 * p + s;
                    float rr = sigm(sg[r * LCN + hcl] + sg2[r * LCN + hcl]);
                    float zz = sigm(sg[r * LCN + 64 + hcl] + sg2[r * LCN + 64 + hcl]);
                    float nn = tanhf(sg[r * LCN + 128 + hcl]
                                   + rr * sg2[r * LCN + 128 + hcl]);
                    float go = ghR[hc * 8 + r];
                    hv[s] = (1.f - zz) * nn + zz * go;
                }
                ull bits = ((ull)__float_as_uint(hv[1]) << 32)
                         | (ull)__float_as_uint(hv[0]);
                float* dp = ghW + hc * 8 + 2 * p;
                *(ull*)dp = bits;
                #pragma unroll
                for (int pr = 0; pr < 4; pr++)
                    if (pr != q) st_peer64(dp, (unsigned)pr, bits);
            }
            CLUSTER_SYNC();
            gpb ^= 1;
        }
    }
}

// ==================== launch ====================
extern "C" void kernel_launch(void* const* d_in, const int* in_sizes, int n_in,
                              void* d_out, int out_size)
{
    const float* z     = (const float*)d_in[0];
    const float* nf    = (const float*)d_in[1];
    const float* u     = (const float*)d_in[2];
    const float* Wih_n = (const float*)d_in[3];
    const float* Whh_n = (const float*)d_in[4];
    const float* bih_n = (const float*)d_in[5];
    const float* bhh_n = (const float*)d_in[6];
    const float* Wih_g = (const float*)d_in[7];
    const float* Whh_g = (const float*)d_in[8];
    const float* bih_g = (const float*)d_in[9];
    const float* bhh_g = (const float*)d_in[10];
    const float* Ws1   = (const float*)d_in[11];
    const float* bs1   = (const float*)d_in[12];
    const float* Ws2   = (const float*)d_in[13];
    const float* bs2   = (const float*)d_in[14];
    float* out = (float*)d_out;

    const long total = 262144L + 196608L * 2 + 1024 + 768 * 2 + 7168 * 2 + 16384
                     + BB * NN + TT + BB * NN * FF + BB * NN * NN + BB * NN;
    int blocks = (int)((total + 255) / 256);
    prep_kernel<<<blocks, 256>>>(nf, Wih_n, Whh_n, bih_n, bhh_n,
                                 Wih_g, Whh_g, bih_g, bhh_g, Ws1, out);

    cudaFuncSetAttribute(chain_kernel,
                         cudaFuncAttributeMaxDynamicSharedMemorySize, SMEM_BYTES);
    chain_kernel<<<NCTA, NT, SMEM_BYTES>>>(z, u, bs1, Ws2, bs2, out);
}

// round 8
// speedup vs baseline: 2.2595x; 1.2248x over previous
#include <cuda_runtime.h>
#include <math.h>

// ---------------- problem constants ----------------
#define BB 256
#define NN 32
#define HH 256
#define FF 7
#define TT 496
#define RR 8                 // batch rows per 4-CTA cluster
#define NCLUST (BB / RR)     // 32 clusters
#define NCTA (NCLUST * 4)    // 128 CTAs
#define NT 512
#define KQN 32               // node k per octant (8-way K split)
#define KQG 64               // graph k per quarter (4-way per matrix)
#define KQS 64               // score k per quarter
#define EPSF 1.1920929e-07f

typedef unsigned long long ull;

// ---------------- device scratch ----------------
// gate-interleaved layouts: local col index lc = hcol*4 + gate
__device__ float g_Wc4[4 * HH * 256];    // node combined weights [q][k][lc]
__device__ float g_Wgi4[4 * HH * 256];   // graph Wih [q][k][lc], gate3 = 0
__device__ float g_Wgh4[4 * HH * 256];   // graph Whh [q][k][lc], gate3 = 0
__device__ float g_bv4[4 * 256];         // node combined bias
__device__ float g_bgi4[4 * 256];        // graph ih bias (gate3 = 0)
__device__ float g_bgh4[4 * 256];        // graph hh bias (gate3 = 0)
__device__ float g_PQi4[4 * FF * 256];   // one-hot(i) gathers (gate3 = 0)
__device__ float g_PQj4[4 * FF * 256];
__device__ float g_Ws1T[HH * 64];        // Ws1 transposed [k][u]
__device__ int   g_idx[BB * NN];
__device__ int   g_rd[TT];
__device__ int   g_cd[TT];

// output layout (float32): [x 57344][adj 262144][batch 8192]
#define OUT_X 0
#define OUT_ADJ 57344
#define OUT_BATCH 319488

// ==================== prep kernel ====================
__global__ void prep_kernel(
    const float* __restrict__ nf,
    const float* __restrict__ Wih_n, const float* __restrict__ Whh_n,
    const float* __restrict__ bih_n, const float* __restrict__ bhh_n,
    const float* __restrict__ Wih_g, const float* __restrict__ Whh_g,
    const float* __restrict__ bih_g, const float* __restrict__ bhh_g,
    const float* __restrict__ Ws1,
    float* __restrict__ out)
{
    long t = (long)blockIdx.x * blockDim.x + threadIdx.x;

    if (t < 262144) {   // g_Wc4: [q][k][col*4+g]
        int q = (int)(t >> 16), k = (int)((t >> 8) & 255), lc = (int)(t & 255);
        int g = lc & 3, col = lc >> 2, hc = q * 64 + col;
        float v;
        if (g == 0)      v = Wih_n[hc * 270 + 14 + k] + Whh_n[hc * 256 + k];
        else if (g == 1) v = Wih_n[(256 + hc) * 270 + 14 + k] + Whh_n[(256 + hc) * 256 + k];
        else if (g == 2) v = Wih_n[(512 + hc) * 270 + 14 + k];
        else             v = Whh_n[(512 + hc) * 256 + k];
        g_Wc4[t] = v; return;
    }
    t -= 262144;
    if (t < 262144) {   // g_Wgi4
        int q = (int)(t >> 16), k = (int)((t >> 8) & 255), lc = (int)(t & 255);
        int g = lc & 3, col = lc >> 2, hc = q * 64 + col;
        g_Wgi4[t] = (g < 3) ? Wih_g[(g * 256 + hc) * 256 + k] : 0.f; return;
    }
    t -= 262144;
    if (t < 262144) {   // g_Wgh4
        int q = (int)(t >> 16), k = (int)((t >> 8) & 255), lc = (int)(t & 255);
        int g = lc & 3, col = lc >> 2, hc = q * 64 + col;
        g_Wgh4[t] = (g < 3) ? Whh_g[(g * 256 + hc) * 256 + k] : 0.f; return;
    }
    t -= 262144;
    if (t < 1024) {     // g_bv4
        int q = (int)(t >> 8), lc = (int)(t & 255);
        int g = lc & 3, col = lc >> 2, hc = q * 64 + col;
        float v;
        if (g == 0)      v = bih_n[hc] + bhh_n[hc];
        else if (g == 1) v = bih_n[256 + hc] + bhh_n[256 + hc];
        else if (g == 2) v = bih_n[512 + hc];
        else             v = bhh_n[512 + hc];
        g_bv4[t] = v; return;
    }
    t -= 1024;
    if (t < 1024) {     // g_bgi4
        int q = (int)(t >> 8), lc = (int)(t & 255);
        int g = lc & 3, col = lc >> 2, hc = q * 64 + col;
        g_bgi4[t] = (g < 3) ? bih_g[g * 256 + hc] : 0.f; return;
    }
    t -= 1024;
    if (t < 1024) {     // g_bgh4
        int q = (int)(t >> 8), lc = (int)(t & 255);
        int g = lc & 3, col = lc >> 2, hc = q * 64 + col;
        g_bgh4[t] = (g < 3) ? bhh_g[g * 256 + hc] : 0.f; return;
    }
    t -= 1024;
    if (t < 7168) {     // g_PQi4: [q][f][lc]
        int q = (int)(t / 1792), rem = (int)(t % 1792);
        int f = rem >> 8, lc = rem & 255;
        int g = lc & 3, col = lc >> 2, hc = q * 64 + col;
        g_PQi4[t] = (g < 3) ? Wih_n[(g * 256 + hc) * 270 + f] : 0.f; return;
    }
    t -= 7168;
    if (t < 7168) {     // g_PQj4
        int q = (int)(t / 1792), rem = (int)(t % 1792);
        int f = rem >> 8, lc = rem & 255;
        int g = lc & 3, col = lc >> 2, hc = q * 64 + col;
        g_PQj4[t] = (g < 3) ? Wih_n[(g * 256 + hc) * 270 + 7 + f] : 0.f; return;
    }
    t -= 7168;
    if (t < 16384) {    // W1T [k][u]
        int k = (int)(t >> 6), u = (int)(t & 63);
        g_Ws1T[t] = Ws1[u * 256 + k]; return;
    }
    t -= 16384;
    if (t < BB * NN) {  // argmax one-hot
        const float* p = nf + t * FF;
        int best = 0;
        #pragma unroll
        for (int f = 0; f < FF; f++) if (p[f] > 0.5f) best = f;
        g_idx[t] = best; return;
    }
    t -= BB * NN;
    if (t < TT) {       // anti-diagonal placement
        int m = (int)t;
        int d = (int)((1.0 + sqrt(1.0 + 8.0 * (double)m)) * 0.5);
        while (d * (d - 1) / 2 > m) d--;
        while ((d + 1) * d / 2 <= m) d++;
        int rr = m - d * (d - 1) / 2;
        g_rd[m] = rr; g_cd[m] = rr + NN - d; return;
    }
    t -= TT;
    if (t < BB * NN * FF) { out[OUT_X + t] = nf[t]; return; }
    t -= BB * NN * FF;
    if (t < BB * NN * NN) { out[OUT_ADJ + t] = 0.f; return; }
    t -= BB * NN * NN;
    if (t < BB * NN) { out[OUT_BATCH + t] = (float)(t >> 5); return; }
}

// ==================== helpers ====================
__device__ __forceinline__ float sigm(float x) { return 1.f / (1.f + expf(-x)); }

__device__ __forceinline__ void ffma2(ull& d, ull a, ull b) {
    asm("fma.rn.f32x2 %0, %1, %2, %0;" : "+l"(d) : "l"(a), "l"(b));
}
__device__ __forceinline__ void fadd2(ull& d, ull a) {
    asm("add.rn.f32x2 %0, %0, %1;" : "+l"(d) : "l"(a));
}
__device__ __forceinline__ ull dup2(float w) {
    ull r;
    asm("mov.b64 %0, {%1, %1};" : "=l"(r) : "r"(__float_as_uint(w)));
    return r;
}
__device__ __forceinline__ float2 unpk(ull v) {
    float2 r;
    r.x = __uint_as_float((unsigned)(v & 0xffffffffu));
    r.y = __uint_as_float((unsigned)(v >> 32));
    return r;
}
__device__ __forceinline__ void st_peer64(float* p, unsigned peer, ull bits) {
    unsigned la = (unsigned)__cvta_generic_to_shared(p);
    unsigned ra;
    asm volatile("mapa.shared::cluster.u32 %0, %1, %2;" : "=r"(ra) : "r"(la), "r"(peer));
    asm volatile("st.shared::cluster.b64 [%0], %1;" :: "r"(ra), "l"(bits) : "memory");
}
#define CLUSTER_SYNC() do { \
    asm volatile("barrier.cluster.arrive.aligned;" ::: "memory"); \
    asm volatile("barrier.cluster.wait.aligned;" ::: "memory"); } while (0)

// ---- gemm core: one thread owns 4 gate-cols of one h-col ----
// acc[g*4 + p] = f32x2 over rows (2p, 2p+1), gate g.
__device__ __forceinline__ void gbody(const float4 w, const float* __restrict__ hk,
                                      ull acc[16])
{
    ulonglong2 h01 = *(const ulonglong2*)(hk);
    ulonglong2 h23 = *(const ulonglong2*)(hk + 4);
    ull wd;
    wd = dup2(w.x);
    ffma2(acc[0], wd, h01.x); ffma2(acc[1], wd, h01.y);
    ffma2(acc[2], wd, h23.x); ffma2(acc[3], wd, h23.y);
    wd = dup2(w.y);
    ffma2(acc[4], wd, h01.x); ffma2(acc[5], wd, h01.y);
    ffma2(acc[6], wd, h23.x); ffma2(acc[7], wd, h23.y);
    wd = dup2(w.z);
    ffma2(acc[8],  wd, h01.x); ffma2(acc[9],  wd, h01.y);
    ffma2(acc[10], wd, h23.x); ffma2(acc[11], wd, h23.y);
    wd = dup2(w.w);
    ffma2(acc[12], wd, h01.x); ffma2(acc[13], wd, h01.y);
    ffma2(acc[14], wd, h23.x); ffma2(acc[15], wd, h23.y);
}

// streamed gemm over NK k-rows, weights from global (stride 256 floats/k)
template <int NK>
__device__ __forceinline__ void gemm_glob(const float* __restrict__ Wp,
                                          const float* __restrict__ hq, ull acc[16])
{
    float4 wb[4];
    #pragma unroll
    for (int x = 0; x < 4; x++) wb[x] = *(const float4*)(Wp + x * 256);
    #pragma unroll
    for (int blk = 0; blk < NK / 4; blk++) {
        float4 wc[4];
        #pragma unroll
        for (int x = 0; x < 4; x++) wc[x] = wb[x];
        if (blk + 1 < NK / 4) {
            const float* np = Wp + (blk + 1) * 4 * 256;
            #pragma unroll
            for (int x = 0; x < 4; x++) wb[x] = *(const float4*)(np + x * 256);
        }
        const float* hkb = hq + blk * 4 * 8;
        #pragma unroll
        for (int x = 0; x < 4; x++) gbody(wc[x], hkb + x * 8, acc);
    }
}

// ---------------- smem layout (float offsets) ----------------
#define SO_WC0  0                          // 32*256 = 8192 (node octant-0 weights)
#define SO_W1T  (SO_WC0 + KQN * 256)       // 8192
#define SO_HA   (SO_W1T + 16384)           // 24576
#define SO_HB   (SO_HA + 2048)             // 26624
#define SO_GA   (SO_HB + 2048)             // 28672
#define SO_GB   (SO_GA + 2048)             // 30720
#define SO_RED  (SO_GB + 2048)             // 32768  64 slots x 256
#define SO_PQI  (SO_RED + 16384)           // 49152
#define SO_PQJ  (SO_PQI + 1792)            // 50944
#define SO_SPS  (SO_PQJ + 1792)            // 52736  score partials 3*128
#define SO_SP4  (SO_SPS + 384)             // 53120
#define SO_IDX  (SO_SP4 + 8)               // 53128  256 ints
#define SMEM_FLOATS (SO_IDX + 256)         // 53384
#define SMEM_BYTES (SMEM_FLOATS * 4)       // 213536

// ==================== main chain kernel ====================
__global__ void __launch_bounds__(NT, 1) __cluster_dims__(4, 1, 1)
chain_kernel(const float* __restrict__ z, const float* __restrict__ uin,
             const float* __restrict__ bs1, const float* __restrict__ Ws2,
             const float* __restrict__ bs2, float* __restrict__ out)
{
    extern __shared__ float sm[];
    float* sWc0 = sm + SO_WC0;
    float* sW1T = sm + SO_W1T;
    float* hBuf[2] = { sm + SO_HA, sm + SO_HB };
    float* gBuf[2] = { sm + SO_GA, sm + SO_GB };
    float* sred = sm + SO_RED;
    float* sPQi = sm + SO_PQI;
    float* sPQj = sm + SO_PQJ;
    float* sps  = sm + SO_SPS;
    float* sp4  = sm + SO_SP4;
    int*   sidx = (int*)(sm + SO_IDX);

    const int t = threadIdx.x;
    const int q = blockIdx.x & 3;
    const int cid = blockIdx.x >> 2;
    const int b0 = cid * RR;

    const float* WcG  = g_Wc4  + q * 65536;
    const float* WgiG = g_Wgi4 + q * 65536;
    const float* WghG = g_Wgh4 + q * 65536;

    // ---- init smem ----
    for (int x = t; x < KQN * 256; x += NT) sWc0[x] = WcG[x];
    for (int x = t; x < 16384; x += NT) sW1T[x] = g_Ws1T[x];
    for (int x = t; x < FF * 256; x += NT) {
        sPQi[x] = g_PQi4[q * FF * 256 + x];
        sPQj[x] = g_PQj4[q * FF * 256 + x];
    }
    for (int x = t; x < 2048; x += NT) {      // graph h init [k][8]
        int k = x >> 3, r = x & 7;
        gBuf[0][x] = z[(b0 + r) * HH + k];
    }
    if (t < RR * NN) sidx[t] = g_idx[b0 * NN + t];

    // gemm role
    const int col = t & 63;
    const int oct = t >> 6;
    // reduce/activation role (t < 128)
    const int ph = oct & 1;                 // row-half 0/1 (rows 4ph..4ph+3)
    const int hc = q * 64 + col;
    // score role
    const int su  = t & 63;
    const int srow = (t >> 6) & 1;
    const int skq = t >> 7;

    // reduce-thread constants (biases)
    float bva[4]  = {0,0,0,0};
    float bgia[4] = {0,0,0,0};
    float bgha[4] = {0,0,0,0};
    if (t < 128) {
        float4 b;
        b = *(const float4*)(g_bv4  + q * 256 + col * 4);
        bva[0]=b.x; bva[1]=b.y; bva[2]=b.z; bva[3]=b.w;
        b = *(const float4*)(g_bgi4 + q * 256 + col * 4);
        bgia[0]=b.x; bgia[1]=b.y; bgia[2]=b.z; bgia[3]=b.w;
        b = *(const float4*)(g_bgh4 + q * 256 + col * 4);
        bgha[0]=b.x; bgha[1]=b.y; bgha[2]=b.z; bgha[3]=b.w;
    }
    const float b1r  = (t < 128) ? bs1[su] : 0.f;
    const float w2r  = (t < 128) ? Ws2[su] : 0.f;
    const float bs2v = *bs2;
    __syncthreads();
    CLUSTER_SYNC();

    int pb = 0, gpb = 0;

    for (int i = 0; i < NN - 1; i++) {
        pb = 0;
        {   // node_h := graph_h
            const float* gs = gBuf[gpb];
            float* d = hBuf[0];
            for (int x = t; x < 2048; x += NT) d[x] = gs[x];
        }
        __syncthreads();

        int fiR[4];
        if (t < 128) {
            #pragma unroll
            for (int r = 0; r < 4; r++) fiR[r] = sidx[(ph * 4 + r) * NN + i];
        }

        for (int j = i + 1; j < NN; j++) {
            float* hR = hBuf[pb];
            float* hW = hBuf[pb ^ 1];

            // ---- node gemm: octant oct, k in [oct*32, oct*32+32) ----
            ull acc[16];
            #pragma unroll
            for (int x = 0; x < 16; x++) acc[x] = 0ull;
            const float* hq = hR + oct * KQN * 8;
            if (oct == 0) {
                const float* wp = sWc0 + col * 4;
                #pragma unroll 4
                for (int k = 0; k < KQN; k++)
                    gbody(*(const float4*)(wp + k * 256), hq + k * 8, acc);
            } else {
                gemm_glob<KQN>(WcG + oct * KQN * 256 + col * 4, hq, acc);
            }
            // stage partials: slot = oct*8 + g*2 + p2, conflict-free STS.128
            #pragma unroll
            for (int g = 0; g < 4; g++) {
                #pragma unroll
                for (int p2 = 0; p2 < 2; p2++) {
                    *(ulonglong2*)(sred + ((oct * 8 + g * 2 + p2) * 256 + col * 4)) =
                        make_ulonglong2(acc[g * 4 + 2 * p2], acc[g * 4 + 2 * p2 + 1]);
                }
            }
            __syncthreads();

            // ---- reduce + in-register GRU activation (t < 128) ----
            if (t < 128) {
                ull s0[4], s1[4];
                #pragma unroll
                for (int g = 0; g < 4; g++) {
                    s0[g] = 0ull; s1[g] = 0ull;
                    #pragma unroll
                    for (int o = 0; o < 8; o++) {
                        ulonglong2 v = *(const ulonglong2*)
                            (sred + ((o * 8 + g * 2 + ph) * 256 + col * 4));
                        fadd2(s0[g], v.x); fadd2(s1[g], v.y);
                    }
                }
                float vg[4][4];
                #pragma unroll
                for (int g = 0; g < 4; g++) {
                    float2 a = unpk(s0[g]), b = unpk(s1[g]);
                    vg[g][0] = a.x + bva[g]; vg[g][1] = a.y + bva[g];
                    vg[g][2] = b.x + bva[g]; vg[g][3] = b.y + bva[g];
                }
                #pragma unroll
                for (int r = 0; r < 4; r++) {
                    int rb = ph * 4 + r;
                    int fj = sidx[rb * NN + j];
                    float4 pi = *(const float4*)(sPQi + fiR[r] * 256 + col * 4);
                    float4 pj = *(const float4*)(sPQj + fj * 256 + col * 4);
                    vg[0][r] += pi.x + pj.x;
                    vg[1][r] += pi.y + pj.y;
                    vg[2][r] += pi.z + pj.z;
                    // gate3 tables are zero
                }
                float4 ho4 = *(const float4*)(hR + hc * 8 + ph * 4);
                float ho[4] = { ho4.x, ho4.y, ho4.z, ho4.w };
                float hn[4];
                #pragma unroll
                for (int r = 0; r < 4; r++) {
                    float gr = sigm(vg[0][r]);
                    float gz = sigm(vg[1][r]);
                    float gn = tanhf(vg[2][r] + gr * vg[3][r]);
                    hn[r] = (1.f - gz) * gn + gz * ho[r];
                }
                ull lo = ((ull)__float_as_uint(hn[1]) << 32) | (ull)__float_as_uint(hn[0]);
                ull hi = ((ull)__float_as_uint(hn[3]) << 32) | (ull)__float_as_uint(hn[2]);
                float* dp = hW + hc * 8 + ph * 4;
                ((ull*)dp)[0] = lo; ((ull*)dp)[1] = hi;
                #pragma unroll
                for (int pr = 0; pr < 4; pr++) {
                    if (pr != q) {
                        st_peer64(dp, (unsigned)pr, lo);
                        st_peer64(dp + 2, (unsigned)pr, hi);
                    }
                }
            }
            CLUSTER_SYNC();

            // ---- K-split score head: rows 2q, 2q+1 ----
            {
                const int rg = 2 * q + srow;
                const float* hp = hW + rg + skq * KQS * 8;
                const float* wp = sW1T + su + skq * KQS * 64;
                float c0 = 0.f, c1 = 0.f;
                #pragma unroll 8
                for (int k = 0; k < KQS; k += 2) {
                    c0 = fmaf(wp[k * 64],       hp[k * 8],       c0);
                    c1 = fmaf(wp[(k + 1) * 64], hp[(k + 1) * 8], c1);
                }
                float pv = c0 + c1;
                if (skq > 0) sps[(skq - 1) * 128 + (t & 127)] = pv;
                __syncthreads();
                if (t < 128) {
                    float hid = fmaxf(pv + sps[t] + sps[128 + t] + sps[256 + t] + b1r, 0.f);
                    float sp = hid * w2r;
                    #pragma unroll
                    for (int o = 16; o; o >>= 1) sp += __shfl_down_sync(0xffffffffu, sp, o);
                    if ((t & 31) == 0) sp4[t >> 5] = sp;
                    asm volatile("bar.sync 1, 128;" ::: "memory");
                    if (t < 2) {
                        float s = sp4[2 * t] + sp4[2 * t + 1] + bs2v;
                        float prob = sigm(s);
                        int m = i * (NN - 1) - (i * (i - 1)) / 2 + (j - i - 1);
                        int b = b0 + 2 * q + t;
                        float uu = uin[b * TT + m];
                        float pc = fminf(fmaxf(prob, EPSF), 1.f - EPSF);
                        float e;
                        if (pc < 0.499f || pc > 0.501f) {
                            e = (log1pf(-pc + uu * (2.f * pc - 1.f)) - log1pf(-pc))
                              / (logf(pc) - log1pf(-pc));
                        } else {
                            e = uu;
                        }
                        int rr = g_rd[m], cc = g_cd[m];
                        float* adj = out + OUT_ADJ + b * (NN * NN);
                        adj[rr * NN + cc] = e;
                        adj[cc * NN + rr] = e;
                    }
                }
            }
            pb ^= 1;
        }

        // ---- graph GRU: gi (octs 0-3) and gh (octs 4-7) in parallel ----
        if (i < NN - 2) {
            const float* hfin = hBuf[pb];
            const float* ghR = gBuf[gpb];
            float* ghW = gBuf[gpb ^ 1];

            ull acc[16];
            #pragma unroll
            for (int x = 0; x < 16; x++) acc[x] = 0ull;
            if (oct < 4) {
                gemm_glob<KQG>(WgiG + oct * KQG * 256 + col * 4,
                               hfin + oct * KQG * 8, acc);
            } else {
                gemm_glob<KQG>(WghG + (oct - 4) * KQG * 256 + col * 4,
                               ghR + (oct - 4) * KQG * 8, acc);
            }
            #pragma unroll
            for (int g = 0; g < 4; g++) {
                #pragma unroll
                for (int p2 = 0; p2 < 2; p2++) {
                    *(ulonglong2*)(sred + ((oct * 8 + g * 2 + p2) * 256 + col * 4)) =
                        make_ulonglong2(acc[g * 4 + 2 * p2], acc[g * 4 + 2 * p2 + 1]);
                }
            }
            __syncthreads();

            if (t < 128) {
                ull gi0[4], gi1[4], gh0[4], gh1[4];
                #pragma unroll
                for (int g = 0; g < 4; g++) {
                    gi0[g] = gi1[g] = gh0[g] = gh1[g] = 0ull;
                    #pragma unroll
                    for (int o = 0; o < 4; o++) {
                        ulonglong2 v = *(const ulonglong2*)
                            (sred + ((o * 8 + g * 2 + ph) * 256 + col * 4));
                        fadd2(gi0[g], v.x); fadd2(gi1[g], v.y);
                    }
                    #pragma unroll
                    for (int o = 4; o < 8; o++) {
                        ulonglong2 v = *(const ulonglong2*)
                            (sred + ((o * 8 + g * 2 + ph) * 256 + col * 4));
                        fadd2(gh0[g], v.x); fadd2(gh1[g], v.y);
                    }
                }
                float vi[3][4], vh[3][4];
                #pragma unroll
                for (int g = 0; g < 3; g++) {
                    float2 a = unpk(gi0[g]), b = unpk(gi1[g]);
                    vi[g][0] = a.x + bgia[g]; vi[g][1] = a.y + bgia[g];
                    vi[g][2] = b.x + bgia[g]; vi[g][3] = b.y + bgia[g];
                    float2 c = unpk(gh0[g]), d = unpk(gh1[g]);
                    vh[g][0] = c.x + bgha[g]; vh[g][1] = c.y + bgha[g];
                    vh[g][2] = d.x + bgha[g]; vh[g][3] = d.y + bgha[g];
                }
                float4 go4 = *(const float4*)(ghR + hc * 8 + ph * 4);
                float go[4] = { go4.x, go4.y, go4.z, go4.w };
                float hn[4];
                #pragma unroll
                for (int r = 0; r < 4; r++) {
                    float rr = sigm(vi[0][r] + vh[0][r]);
                    float zz = sigm(vi[1][r] + vh[1][r]);
                    float nn = tanhf(vi[2][r] + rr * vh[2][r]);
                    hn[r] = (1.f - zz) * nn + zz * go[r];
                }
                ull lo = ((ull)__float_as_uint(hn[1]) << 32) | (ull)__float_as_uint(hn[0]);
                ull hi = ((ull)__float_as_uint(hn[3]) << 32) | (ull)__float_as_uint(hn[2]);
                float* dp = ghW + hc * 8 + ph * 4;
                ((ull*)dp)[0] = lo; ((ull*)dp)[1] = hi;
                #pragma unroll
                for (int pr = 0; pr < 4; pr++) {
                    if (pr != q) {
                        st_peer64(dp, (unsigned)pr, lo);
                        st_peer64(dp + 2, (unsigned)pr, hi);
                    }
                }
            }
            CLUSTER_SYNC();
            gpb ^= 1;
        }
    }
}

// ==================== launch ====================
extern "C" void kernel_launch(void* const* d_in, const int* in_sizes, int n_in,
                              void* d_out, int out_size)
{
    const float* z     = (const float*)d_in[0];
    const float* nf    = (const float*)d_in[1];
    const float* u     = (const float*)d_in[2];
    const float* Wih_n = (const float*)d_in[3];
    const float* Whh_n = (const float*)d_in[4];
    const float* bih_n = (const float*)d_in[5];
    const float* bhh_n = (const float*)d_in[6];
    const float* Wih_g = (const float*)d_in[7];
    const float* Whh_g = (const float*)d_in[8];
    const float* bih_g = (const float*)d_in[9];
    const float* bhh_g = (const float*)d_in[10];
    const float* Ws1   = (const float*)d_in[11];
    const float* bs1   = (const float*)d_in[12];
    const float* Ws2   = (const float*)d_in[13];
    const float* bs2   = (const float*)d_in[14];
    float* out = (float*)d_out;

    const long total = 262144L * 3 + 1024 * 3 + 7168 * 2 + 16384
                     + BB * NN + TT + BB * NN * FF + BB * NN * NN + BB * NN;
    int blocks = (int)((total + 255) / 256);
    prep_kernel<<<blocks, 256>>>(nf, Wih_n, Whh_n, bih_n, bhh_n,
                                 Wih_g, Whh_g, bih_g, bhh_g, Ws1, out);

    cudaFuncSetAttribute(chain_kernel,
                         cudaFuncAttributeMaxDynamicSharedMemorySize, SMEM_BYTES);
    chain_kernel<<<NCTA, NT, SMEM_BYTES>>>(z, u, bs1, Ws2, bs2, out);
}